// round 10
// baseline (speedup 1.0000x reference)
#include <cuda_runtime.h>
#include <cuda_fp16.h>
#include <cstdint>

// Problem constants
#define DM   1024
#define DI   2048
#define DS   16
#define BB   2
#define LL   2048
#define MM   (BB*LL)         // 4096 tokens
#define GCH  8               // scan chunks
#define CLEN (LL/GCH)        // 256 steps per chunk

// ---------------- scratch (device globals) -----------------------------------
__device__ float g_xz [(size_t)MM * 2 * DI];   // x_proj | silu(z)  (fp32)
__device__ float g_dt [(size_t)MM * DI];       // softplus dt       (fp32)
__device__ float g_A2 [DI * DS];               // -exp(A_log)*log2e

// fp16 operand arrays
__device__ __half g_xh   [(size_t)MM * DM];
__device__ __half g_Winh [(size_t)2*DI * DM];
__device__ __half g_Wdth [(size_t)DI * DI];
__device__ __half g_Wouth[(size_t)DM * DI];
__device__ __half g_xacth[(size_t)MM * DI];
__device__ __half g_ygh  [(size_t)MM * DI];

// chunked-scan intermediates
__device__ float g_Sdv [(size_t)BB * DI * GCH];
__device__ float g_hout[(size_t)BB * DI * GCH * DS];
__device__ float g_hin [(size_t)BB * DI * GCH * DS];

// ---------------- scalar helpers ---------------------------------------------
__device__ __forceinline__ float ex2f(float x) {
    float y; asm("ex2.approx.ftz.f32 %0, %1;" : "=f"(y) : "f"(x)); return y;
}
__device__ __forceinline__ float siluf(float v) {
    return __fdividef(v, 1.0f + __expf(-v));
}
__device__ __forceinline__ float softplusf(float v) {
    return (v > 20.0f) ? v : log1pf(__expf(v));
}
__device__ __forceinline__ uint32_t smem_u32(const void* p) {
    uint32_t a;
    asm("{ .reg .u64 t; cvta.to.shared.u64 t, %1; cvt.u32.u64 %0, t; }" : "=r"(a) : "l"(p));
    return a;
}

// ---------------- PTX primitives (baseline ISA only) --------------------------
#define CP16(dst, src) \
    asm volatile("cp.async.cg.shared.global [%0], [%1], 16;" :: "r"(dst), "l"(src) : "memory")
#define CP_COMMIT() asm volatile("cp.async.commit_group;" ::: "memory")
#define CP_WAIT(n)  asm volatile("cp.async.wait_group %0;" :: "n"(n) : "memory")

#define LDSM4(r, addr) \
    asm volatile("ldmatrix.sync.aligned.m8n8.x4.shared.b16 {%0,%1,%2,%3}, [%4];" \
        : "=r"((r)[0]), "=r"((r)[1]), "=r"((r)[2]), "=r"((r)[3]) : "r"(addr))

#define MMA_F16(d, a, b0, b1) \
    asm volatile("mma.sync.aligned.m16n8k16.row.col.f32.f16.f16.f32 " \
        "{%0,%1,%2,%3}, {%4,%5,%6,%7}, {%8,%9}, {%0,%1,%2,%3};" \
        : "+f"((d)[0]), "+f"((d)[1]), "+f"((d)[2]), "+f"((d)[3]) \
        : "r"((a)[0]), "r"((a)[1]), "r"((a)[2]), "r"((a)[3]), "r"(b0), "r"(b1))

#define SWZ(off) ((off) ^ (((off) >> 3) & 0x70))

// ---------------- fp16 NT-GEMM via mma.sync ------------------------------------
// C[M,N] = A[M,K]*B[N,K]^T, single fp16 pass.
// 128x128 CTA tile, BK=64, 256 threads (8 warps: 2M x 4N, 64x32 warp tiles),
// 3-stage cp.async pipeline (96KB SMEM) -> 2 CTAs/SM.
// Rationale (R9 ncu): SMEM LDS bandwidth is the floor (L1=53.8%, 256B/MMA);
// 64x32 warp tiles cut to 192B/MMA; 2 independent CTAs decouple barriers.
static constexpr int STAGE_BYTES = 32768;                // Ah(16K) | Bh(16K)
static constexpr int NSTAGE      = 3;
static constexpr int GEMM_SMEM   = NSTAGE * STAGE_BYTES; // 96KB

template<int N, int K, int EPI>
__global__ void __launch_bounds__(256, 2)
mma_gemm(const __half* __restrict__ Ah, const __half* __restrict__ Bh,
         float* __restrict__ C, const float* __restrict__ bias)
{
    extern __shared__ __align__(1024) uint8_t smem[];
    const uint32_t sb = smem_u32(smem);
    const int tid = threadIdx.x, lane = tid & 31, wid = tid >> 5;
    const int wm = wid & 1, wn = wid >> 1;            // 2M x 4N warp grid
    const int bm = blockIdx.y * 128, bn = blockIdx.x * 128;
    constexpr int NC = K / 64;

    // ---- cp.async mapping: 256 rows per stage (A 128 | B 128), 1 row/thread --
    const __half* gsrc = (tid < 128) ? Ah + (size_t)(bm + tid) * K
                                     : Bh + (size_t)(bn + tid - 128) * K;
    const uint32_t sregion = (tid < 128) ? (uint32_t)tid * 128
                                         : 16384u + (uint32_t)(tid - 128) * 128;
    uint32_t dOff[8];
#pragma unroll
    for (int j = 0; j < 8; j++) dOff[j] = SWZ(sregion + (uint32_t)j * 16);

    // ---- ldmatrix lane offsets ----
    const int rA = (lane & 7) + ((lane >> 3) & 1) * 8;
    const int sA = ((lane >> 4) & 1) * 16;
    const uint32_t aOff = SWZ((uint32_t)(wm * 64 + rA) * 128 + sA);
    const int rB = (lane & 7) + ((lane >> 4) & 1) * 8;
    const int sB = ((lane >> 3) & 1) * 16;
    const uint32_t bOff = SWZ((uint32_t)(wn * 32 + rB) * 128 + sB);

    float acc[4][4][4];   // [mf: 16-row group][nf: 8-col group][quad]
#pragma unroll
    for (int i = 0; i < 4; i++)
#pragma unroll
        for (int j = 0; j < 4; j++)
#pragma unroll
            for (int q = 0; q < 4; q++) acc[i][j][q] = 0.f;

    auto issue = [&](int c) {
        const uint32_t s0 = sb + (uint32_t)(c % NSTAGE) * STAGE_BYTES;
        const int k0 = c * 64;
#pragma unroll
        for (int j = 0; j < 8; j++)
            CP16(s0 + dOff[j], gsrc + k0 + j * 8);
        CP_COMMIT();
    };

    issue(0);
    issue(1);
    for (int c = 0; c < NC; c++) {
        if (c + 2 < NC) { CP_WAIT(1); __syncthreads(); issue(c + 2); }
        else            { CP_WAIT(0); __syncthreads(); }

        const uint32_t s0 = sb + (uint32_t)(c % NSTAGE) * STAGE_BYTES;
        const uint32_t aB = s0 + aOff;
        const uint32_t bB = s0 + 16384u + bOff;
#pragma unroll
        for (int kk = 0; kk < 4; kk++) {
            const uint32_t kx = (uint32_t)kk * 32;
            uint32_t ah[4][4], bh[2][4];
#pragma unroll
            for (int mf = 0; mf < 4; mf++)
                LDSM4(ah[mf], (aB + (uint32_t)mf * 2048) ^ kx);
#pragma unroll
            for (int g = 0; g < 2; g++)
                LDSM4(bh[g], (bB + (uint32_t)g * 2048) ^ kx);
#pragma unroll
            for (int mf = 0; mf < 4; mf++)
#pragma unroll
                for (int g = 0; g < 2; g++)
#pragma unroll
                    for (int h = 0; h < 2; h++)
                        MMA_F16(acc[mf][g * 2 + h], ah[mf], bh[g][2 * h], bh[g][2 * h + 1]);
        }
    }

    // ---- epilogue ----
    const int qr = lane >> 2, qc = lane & 3;
    const bool do_silu = (EPI == 1) && (bn >= (N >> 1));
#pragma unroll
    for (int mf = 0; mf < 4; mf++) {
        const int row0 = bm + wm * 64 + mf * 16 + qr;
#pragma unroll
        for (int p = 0; p < 2; p++) {
            float* cr = C + (size_t)(row0 + p * 8) * N + bn + wn * 32 + qc * 2;
#pragma unroll
            for (int nf = 0; nf < 4; nf++) {
                float vx = acc[mf][nf][2 * p];
                float vy = acc[mf][nf][2 * p + 1];
                if (EPI == 1) {
                    if (do_silu) { vx = siluf(vx); vy = siluf(vy); }
                } else if (EPI == 2) {
                    const int col = bn + wn * 32 + nf * 8 + qc * 2;
                    vx = softplusf(vx + bias[col]);
                    vy = softplusf(vy + bias[col + 1]);
                }
                float2 v; v.x = vx; v.y = vy;
                *(float2*)(cr + nf * 8) = v;
            }
        }
    }
}

// ---------------- fp32 -> fp16 convert (vectorized x4) -------------------------
__global__ void cvt_kernel(const float* __restrict__ in,
                           __half* __restrict__ oh, int n4)
{
    int i = blockIdx.x * blockDim.x + threadIdx.x;
    if (i >= n4) return;
    float4 v = ((const float4*)in)[i];
    ((__half2*)oh)[2 * i]     = __floats2half2_rn(v.x, v.y);
    ((__half2*)oh)[2 * i + 1] = __floats2half2_rn(v.z, v.w);
}

// ---------------- depthwise causal conv + SiLU ---------------------------------
__global__ void conv_silu_kernel(const float* __restrict__ cw,
                                 const float* __restrict__ cb)
{
    int idx = blockIdx.x * blockDim.x + threadIdx.x;
    if (idx >= MM * DI) return;
    const int c = idx & (DI - 1);
    const int m = idx >> 11;
    const int t = m & (LL - 1);

    const float* p = g_xz + (size_t)m * (2 * DI) + c;
    const float4 w = ((const float4*)cw)[c];
    float acc = cb[c] + w.w * p[0];
    if (t >= 1) acc += w.z * p[-(2 * DI)];
    if (t >= 2) acc += w.y * p[-2 * (2 * DI)];
    if (t >= 3) acc += w.x * p[-3 * (2 * DI)];
    g_xacth[idx] = __float2half_rn(siluf(acc));
}

// ---------------- A2 = -exp(A_log) * log2(e) -----------------------------------
__global__ void prep_A2_kernel(const float* __restrict__ A_log)
{
    int i = blockIdx.x * blockDim.x + threadIdx.x;
    if (i < DI * DS) g_A2[i] = -expf(A_log[i]) * 1.4426950408889634f;
}

// ---------------- chunked scan: pass A (per-chunk partials) --------------------
__global__ void __launch_bounds__(128)
scanA_kernel()
{
    const int tid = threadIdx.x;
    const int sg  = tid & 3;
    const int cl  = tid >> 2;
    const int g   = blockIdx.x & (GCH - 1);
    const int cb  = (blockIdx.x >> 3) & 63;
    const int b   = blockIdx.x >> 9;
    const int c   = (cb << 5) + cl;

    float a2[4];
#pragma unroll
    for (int s = 0; s < 4; s++) a2[s] = g_A2[c * DS + sg * 4 + s];

    const size_t base = (size_t)b * LL * DI + (size_t)g * CLEN * DI + c;

    float h0 = 0.f, h1 = 0.f, h2 = 0.f, h3 = 0.f, sdv = 0.f;
    float px[8], pd[8];
#pragma unroll
    for (int u = 0; u < 8; u++) {
        const size_t o = base + (size_t)u * DI;
        px[u] = __half2float(g_xacth[o]);
        pd[u] = g_dt[o];
    }

    for (int t0 = 0; t0 < CLEN; t0 += 8) {
        float cx[8], cd[8];
#pragma unroll
        for (int u = 0; u < 8; u++) { cx[u] = px[u]; cd[u] = pd[u]; }
        if (t0 + 8 < CLEN) {
#pragma unroll
            for (int u = 0; u < 8; u++) {
                const size_t o = base + (size_t)(t0 + 8 + u) * DI;
                px[u] = __half2float(g_xacth[o]);
                pd[u] = g_dt[o];
            }
        }
#pragma unroll
        for (int u = 0; u < 8; u++) {
            const float dv  = cd[u];
            const float dtx = dv * cx[u];
            sdv += dv;
            h0 = ex2f(dv * a2[0]) * h0 + dtx;
            h1 = ex2f(dv * a2[1]) * h1 + dtx;
            h2 = ex2f(dv * a2[2]) * h2 + dtx;
            h3 = ex2f(dv * a2[3]) * h3 + dtx;
        }
    }

    const size_t idx = ((size_t)b * DI + c) * GCH + g;
    if (sg == 0) g_Sdv[idx] = sdv;
    float* ho = g_hout + idx * DS + sg * 4;
    ho[0] = h0; ho[1] = h1; ho[2] = h2; ho[3] = h3;
}

// ---------------- chunked scan: pass B (sequential combine) --------------------
__global__ void __launch_bounds__(256)
scanB_kernel()
{
    const int i = blockIdx.x * blockDim.x + threadIdx.x;
    if (i >= BB * DI * 4) return;
    const int sg = i & 3;
    const int c  = (i >> 2) & (DI - 1);
    const int b  = i >> 13;

    float a2[4];
#pragma unroll
    for (int s = 0; s < 4; s++) a2[s] = g_A2[c * DS + sg * 4 + s];

    float h[4] = {0.f, 0.f, 0.f, 0.f};
    const size_t row = ((size_t)b * DI + c) * GCH;
#pragma unroll
    for (int g = 0; g < GCH; g++) {
        const size_t idx = row + g;
        const float sdv = g_Sdv[idx];
        float* hi = g_hin  + idx * DS + sg * 4;
        const float* ho = g_hout + idx * DS + sg * 4;
#pragma unroll
        for (int s = 0; s < 4; s++) {
            hi[s] = h[s];
            h[s] = ex2f(a2[s] * sdv) * h[s] + ho[s];
        }
    }
}

// ---------------- chunked scan: pass C (recompute + gate) ----------------------
__global__ void __launch_bounds__(128)
scanC_kernel(const float* __restrict__ Dp)
{
    const int tid = threadIdx.x;
    const int sg  = tid & 3;
    const int cl  = tid >> 2;
    const int g   = blockIdx.x & (GCH - 1);
    const int cb  = (blockIdx.x >> 3) & 63;
    const int b   = blockIdx.x >> 9;
    const int c   = (cb << 5) + cl;

    float a2[4];
#pragma unroll
    for (int s = 0; s < 4; s++) a2[s] = g_A2[c * DS + sg * 4 + s];
    const float dpc = Dp[c];

    const size_t base = (size_t)b * LL * DI + (size_t)g * CLEN * DI + c;
    const size_t zoff = (size_t)b * LL * (2 * DI) + (size_t)g * CLEN * (2 * DI) + DI + c;

    const size_t idx = ((size_t)b * DI + c) * GCH + g;
    const float* hi = g_hin + idx * DS + sg * 4;
    float h0 = hi[0], h1 = hi[1], h2 = hi[2], h3 = hi[3];

    float px[8], pd[8];
#pragma unroll
    for (int u = 0; u < 8; u++) {
        const size_t o = base + (size_t)u * DI;
        px[u] = __half2float(g_xacth[o]);
        pd[u] = g_dt[o];
    }

    for (int t0 = 0; t0 < CLEN; t0 += 8) {
        float cx[8], cd[8];
#pragma unroll
        for (int u = 0; u < 8; u++) { cx[u] = px[u]; cd[u] = pd[u]; }
        if (t0 + 8 < CLEN) {
#pragma unroll
            for (int u = 0; u < 8; u++) {
                const size_t o = base + (size_t)(t0 + 8 + u) * DI;
                px[u] = __half2float(g_xacth[o]);
                pd[u] = g_dt[o];
            }
        }
#pragma unroll
        for (int u = 0; u < 8; u++) {
            const float xv  = cx[u];
            const float dv  = cd[u];
            const float dtx = dv * xv;
            h0 = ex2f(dv * a2[0]) * h0 + dtx;
            h1 = ex2f(dv * a2[1]) * h1 + dtx;
            h2 = ex2f(dv * a2[2]) * h2 + dtx;
            h3 = ex2f(dv * a2[3]) * h3 + dtx;
            float sum = (h0 + h1) + (h2 + h3);
            sum += __shfl_xor_sync(0xffffffffu, sum, 1);
            sum += __shfl_xor_sync(0xffffffffu, sum, 2);
            if (sg == 0) {
                const float zs = g_xz[zoff + (size_t)(t0 + u) * (2 * DI)];
                const float v  = (sum + dpc * xv) * zs;
                g_ygh[base + (size_t)(t0 + u) * DI] = __float2half_rn(v);
            }
        }
    }
}

// ---------------- launch -------------------------------------------------------
extern "C" void kernel_launch(void* const* d_in, const int* in_sizes, int n_in,
                              void* d_out, int out_size)
{
    (void)in_sizes; (void)n_in; (void)out_size;
    const float* x     = (const float*)d_in[0];
    const float* W_in  = (const float*)d_in[1];
    const float* cw    = (const float*)d_in[2];
    const float* cb    = (const float*)d_in[3];
    const float* A_log = (const float*)d_in[4];
    const float* Dp    = (const float*)d_in[5];
    const float* W_dt  = (const float*)d_in[6];
    const float* b_dt  = (const float*)d_in[7];
    const float* W_out = (const float*)d_in[8];
    float* out = (float*)d_out;

    float *xz, *dt;
    __half *xh, *winh, *wdth, *wouth, *xacth, *ygh;
    cudaGetSymbolAddress((void**)&xz,    g_xz);
    cudaGetSymbolAddress((void**)&dt,    g_dt);
    cudaGetSymbolAddress((void**)&xh,    g_xh);
    cudaGetSymbolAddress((void**)&winh,  g_Winh);
    cudaGetSymbolAddress((void**)&wdth,  g_Wdth);
    cudaGetSymbolAddress((void**)&wouth, g_Wouth);
    cudaGetSymbolAddress((void**)&xacth, g_xacth);
    cudaGetSymbolAddress((void**)&ygh,   g_ygh);

    cudaFuncSetAttribute(mma_gemm<2 * DI, DM, 1>,
                         cudaFuncAttributeMaxDynamicSharedMemorySize, GEMM_SMEM);
    cudaFuncSetAttribute(mma_gemm<DI, DI, 2>,
                         cudaFuncAttributeMaxDynamicSharedMemorySize, GEMM_SMEM);
    cudaFuncSetAttribute(mma_gemm<DM, DI, 0>,
                         cudaFuncAttributeMaxDynamicSharedMemorySize, GEMM_SMEM);

    // launches #1..#3 (profiler captures the 4th launch -> gemm1)
    prep_A2_kernel<<<(DI * DS + 255) / 256, 256>>>(A_log);
    cvt_kernel<<<(MM * DM / 4 + 255) / 256, 256>>>(x,    xh,   MM * DM / 4);
    cvt_kernel<<<(2 * DI * DM / 4 + 255) / 256, 256>>>(W_in, winh, 2 * DI * DM / 4);

    // #4: GEMM1: xz = x @ W_in^T  (silu fused on z half)   <-- profiled
    mma_gemm<2 * DI, DM, 1><<<dim3((2 * DI) / 128, MM / 128), 256, GEMM_SMEM>>>(
        xh, winh, xz, nullptr);

    cvt_kernel<<<(DI * DI / 4 + 255) / 256, 256>>>(W_dt, wdth, DI * DI / 4);
    conv_silu_kernel<<<(MM * DI + 255) / 256, 256>>>(cw, cb);

    // GEMM2: dt = softplus(x_act @ W_dt^T + b_dt)
    mma_gemm<DI, DI, 2><<<dim3(DI / 128, MM / 128), 256, GEMM_SMEM>>>(
        xacth, wdth, dt, b_dt);

    cvt_kernel<<<(DM * DI / 4 + 255) / 256, 256>>>(W_out, wouth, DM * DI / 4);

    // chunked scan
    scanA_kernel<<<BB * (DI / 32) * GCH, 128>>>();
    scanB_kernel<<<(BB * DI * 4 + 255) / 256, 256>>>();
    scanC_kernel<<<BB * (DI / 32) * GCH, 128>>>(Dp);

    // GEMM3: out = yg @ W_out^T
    mma_gemm<DM, DI, 0><<<dim3(DM / 128, MM / 128), 256, GEMM_SMEM>>>(
        ygh, wouth, out, nullptr);
}

// round 11
// speedup vs baseline: 1.2357x; 1.2357x over previous
#include <cuda_runtime.h>
#include <cuda_fp16.h>
#include <cstdint>

// Problem constants
#define DM   1024
#define DI   2048
#define DS   16
#define BB   2
#define LL   2048
#define MM   (BB*LL)         // 4096 tokens
#define GCH  8               // scan chunks
#define CLEN (LL/GCH)        // 256 steps per chunk

// ---------------- scratch (device globals) -----------------------------------
__device__ float g_xz [(size_t)MM * 2 * DI];   // x_proj | silu(z)  (fp32)
__device__ float g_dt [(size_t)MM * DI];       // softplus dt       (fp32)
__device__ float g_A2 [DI * DS];               // -exp(A_log)*log2e

// fp16 operand arrays
__device__ __half g_xh   [(size_t)MM * DM];
__device__ __half g_Winh [(size_t)2*DI * DM];
__device__ __half g_Wdth [(size_t)DI * DI];
__device__ __half g_Wouth[(size_t)DM * DI];
__device__ __half g_xacth[(size_t)MM * DI];
__device__ __half g_ygh  [(size_t)MM * DI];

// chunked-scan intermediates
__device__ float g_Sdv [(size_t)BB * DI * GCH];
__device__ float g_hout[(size_t)BB * DI * GCH * DS];
__device__ float g_hin [(size_t)BB * DI * GCH * DS];

// ---------------- scalar helpers ---------------------------------------------
__device__ __forceinline__ float ex2f(float x) {
    float y; asm("ex2.approx.ftz.f32 %0, %1;" : "=f"(y) : "f"(x)); return y;
}
__device__ __forceinline__ float siluf(float v) {
    return __fdividef(v, 1.0f + __expf(-v));
}
__device__ __forceinline__ float softplusf(float v) {
    return (v > 20.0f) ? v : log1pf(__expf(v));
}
__device__ __forceinline__ uint32_t smem_u32(const void* p) {
    uint32_t a;
    asm("{ .reg .u64 t; cvta.to.shared.u64 t, %1; cvt.u32.u64 %0, t; }" : "=r"(a) : "l"(p));
    return a;
}

// ---------------- PTX primitives (baseline ISA only) --------------------------
#define CP16(dst, src) \
    asm volatile("cp.async.cg.shared.global [%0], [%1], 16;" :: "r"(dst), "l"(src) : "memory")
#define CP_COMMIT() asm volatile("cp.async.commit_group;" ::: "memory")
#define CP_WAIT(n)  asm volatile("cp.async.wait_group %0;" :: "n"(n) : "memory")

#define LDSM4(r, addr) \
    asm volatile("ldmatrix.sync.aligned.m8n8.x4.shared.b16 {%0,%1,%2,%3}, [%4];" \
        : "=r"((r)[0]), "=r"((r)[1]), "=r"((r)[2]), "=r"((r)[3]) : "r"(addr))

#define MMA_F16(d, a, b0, b1) \
    asm volatile("mma.sync.aligned.m16n8k16.row.col.f32.f16.f16.f32 " \
        "{%0,%1,%2,%3}, {%4,%5,%6,%7}, {%8,%9}, {%0,%1,%2,%3};" \
        : "+f"((d)[0]), "+f"((d)[1]), "+f"((d)[2]), "+f"((d)[3]) \
        : "r"((a)[0]), "r"((a)[1]), "r"((a)[2]), "r"((a)[3]), "r"(b0), "r"(b1))

#define SWZ(off) ((off) ^ (((off) >> 3) & 0x70))

// ---------------- fp16 NT-GEMM via mma.sync ------------------------------------
// C[M,N] = A[M,K]*B[N,K]^T, single fp16 pass.
// R9 tiling (proven optimum): 128x128 CTA tile, BK=64, 512 threads
// (16 warps: 4M x 4N, 32x32 warp tiles), 6-stage cp.async (192KB).
// NEW: kk-level fragment double-buffering — prefetch kk+1's LDSM fragments
// while issuing kk's MMAs (R9 issue=19.7% -> LDSM latency was exposed).
static constexpr int STAGE_BYTES = 32768;                // Ah(16K) | Bh(16K)
static constexpr int NSTAGE      = 6;
static constexpr int GEMM_SMEM   = NSTAGE * STAGE_BYTES; // 192KB

template<int N, int K, int EPI>
__global__ void __launch_bounds__(512, 1)
mma_gemm(const __half* __restrict__ Ah, const __half* __restrict__ Bh,
         float* __restrict__ C, const float* __restrict__ bias)
{
    extern __shared__ __align__(1024) uint8_t smem[];
    const uint32_t sb = smem_u32(smem);
    const int tid = threadIdx.x, lane = tid & 31, wid = tid >> 5;
    const int wm = wid & 3, wn = wid >> 2;            // 4 x 4 warp grid
    const int bm = blockIdx.y * 128, bn = blockIdx.x * 128;
    constexpr int NC = K / 64;

    // ---- cp.async mapping: per stage 2 arrays x 128 rows x 128B ---------------
    const int lrow = tid >> 2;                 // 0..127
    const int gp   = (tid & 3) * 2;            // 2 x 16B granules per array
    uint32_t dOff[2];
#pragma unroll
    for (int j = 0; j < 2; j++)
        dOff[j] = SWZ((uint32_t)lrow * 128 + (uint32_t)(gp + j) * 16);

    const __half* gAh = Ah + (size_t)(bm + lrow) * K;
    const __half* gBh = Bh + (size_t)(bn + lrow) * K;

    // ---- ldmatrix lane offsets ----
    const int rA = (lane & 7) + ((lane >> 3) & 1) * 8;
    const int sA = ((lane >> 4) & 1) * 16;
    const uint32_t aOff = SWZ((uint32_t)(wm * 32 + rA) * 128 + sA);
    const int rB = (lane & 7) + ((lane >> 4) & 1) * 8;
    const int sB = ((lane >> 3) & 1) * 16;
    const uint32_t bOff = SWZ((uint32_t)(wn * 32 + rB) * 128 + sB);

    float acc[2][4][4];
#pragma unroll
    for (int i = 0; i < 2; i++)
#pragma unroll
        for (int j = 0; j < 4; j++)
#pragma unroll
            for (int q = 0; q < 4; q++) acc[i][j][q] = 0.f;

    auto issue = [&](int c) {
        const uint32_t s0 = sb + (uint32_t)(c % NSTAGE) * STAGE_BYTES;
        const int k0 = c * 64;
#pragma unroll
        for (int j = 0; j < 2; j++) {
            const int ke = k0 + (gp + j) * 8;
            CP16(s0 +         dOff[j], gAh + ke);
            CP16(s0 + 16384 + dOff[j], gBh + ke);
        }
        CP_COMMIT();
    };

#pragma unroll
    for (int s = 0; s < NSTAGE - 1 && s < NC; s++) issue(s);

    for (int c = 0; c < NC; c++) {
        if (c + NSTAGE - 1 < NC) { CP_WAIT(NSTAGE - 2); __syncthreads(); issue(c + NSTAGE - 1); }
        else                     { CP_WAIT(0); __syncthreads(); }

        const uint32_t s0 = sb + (uint32_t)(c % NSTAGE) * STAGE_BYTES;
        const uint32_t aB = s0 + aOff;
        const uint32_t bB = s0 + 16384 + bOff;

        // fragment double-buffer across the 4 kk-steps
        uint32_t ah[2][2][4], bh[2][2][4];
        LDSM4(ah[0][0], aB);
        LDSM4(ah[0][1], aB + 2048u);
        LDSM4(bh[0][0], bB);
        LDSM4(bh[0][1], bB + 2048u);
#pragma unroll
        for (int kk = 0; kk < 4; kk++) {
            const int cur = kk & 1, nxt = cur ^ 1;
            if (kk < 3) {
                const uint32_t kx = (uint32_t)(kk + 1) * 32;
                LDSM4(ah[nxt][0], aB ^ kx);
                LDSM4(ah[nxt][1], (aB + 2048u) ^ kx);
                LDSM4(bh[nxt][0], bB ^ kx);
                LDSM4(bh[nxt][1], (bB + 2048u) ^ kx);
            }
#pragma unroll
            for (int mf = 0; mf < 2; mf++)
#pragma unroll
                for (int g = 0; g < 2; g++)
#pragma unroll
                    for (int h = 0; h < 2; h++)
                        MMA_F16(acc[mf][g * 2 + h], ah[cur][mf],
                                bh[cur][g][2 * h], bh[cur][g][2 * h + 1]);
        }
    }

    // ---- epilogue ----
    const int qr = lane >> 2, qc = lane & 3;
    const bool do_silu = (EPI == 1) && (bn >= (N >> 1));
#pragma unroll
    for (int mf = 0; mf < 2; mf++) {
        const int row0 = bm + wm * 32 + mf * 16 + qr;
#pragma unroll
        for (int p = 0; p < 2; p++) {
            float* cr = C + (size_t)(row0 + p * 8) * N + bn + wn * 32 + qc * 2;
#pragma unroll
            for (int nf = 0; nf < 4; nf++) {
                float vx = acc[mf][nf][2 * p];
                float vy = acc[mf][nf][2 * p + 1];
                if (EPI == 1) {
                    if (do_silu) { vx = siluf(vx); vy = siluf(vy); }
                } else if (EPI == 2) {
                    const int col = bn + wn * 32 + nf * 8 + qc * 2;
                    vx = softplusf(vx + bias[col]);
                    vy = softplusf(vy + bias[col + 1]);
                }
                float2 v; v.x = vx; v.y = vy;
                *(float2*)(cr + nf * 8) = v;
            }
        }
    }
}

// ---------------- fp32 -> fp16 convert (vectorized x4) -------------------------
__global__ void cvt_kernel(const float* __restrict__ in,
                           __half* __restrict__ oh, int n4)
{
    int i = blockIdx.x * blockDim.x + threadIdx.x;
    if (i >= n4) return;
    float4 v = ((const float4*)in)[i];
    ((__half2*)oh)[2 * i]     = __floats2half2_rn(v.x, v.y);
    ((__half2*)oh)[2 * i + 1] = __floats2half2_rn(v.z, v.w);
}

// ---------------- depthwise causal conv + SiLU ---------------------------------
__global__ void conv_silu_kernel(const float* __restrict__ cw,
                                 const float* __restrict__ cb)
{
    int idx = blockIdx.x * blockDim.x + threadIdx.x;
    if (idx >= MM * DI) return;
    const int c = idx & (DI - 1);
    const int m = idx >> 11;
    const int t = m & (LL - 1);

    const float* p = g_xz + (size_t)m * (2 * DI) + c;
    const float4 w = ((const float4*)cw)[c];
    float acc = cb[c] + w.w * p[0];
    if (t >= 1) acc += w.z * p[-(2 * DI)];
    if (t >= 2) acc += w.y * p[-2 * (2 * DI)];
    if (t >= 3) acc += w.x * p[-3 * (2 * DI)];
    g_xacth[idx] = __float2half_rn(siluf(acc));
}

// ---------------- A2 = -exp(A_log) * log2(e) -----------------------------------
__global__ void prep_A2_kernel(const float* __restrict__ A_log)
{
    int i = blockIdx.x * blockDim.x + threadIdx.x;
    if (i < DI * DS) g_A2[i] = -expf(A_log[i]) * 1.4426950408889634f;
}

// ---------------- chunked scan: pass A (per-chunk partials) --------------------
__global__ void __launch_bounds__(128)
scanA_kernel()
{
    const int tid = threadIdx.x;
    const int sg  = tid & 3;
    const int cl  = tid >> 2;
    const int g   = blockIdx.x & (GCH - 1);
    const int cb  = (blockIdx.x >> 3) & 63;
    const int b   = blockIdx.x >> 9;
    const int c   = (cb << 5) + cl;

    float a2[4];
#pragma unroll
    for (int s = 0; s < 4; s++) a2[s] = g_A2[c * DS + sg * 4 + s];

    const size_t base = (size_t)b * LL * DI + (size_t)g * CLEN * DI + c;

    float h0 = 0.f, h1 = 0.f, h2 = 0.f, h3 = 0.f, sdv = 0.f;
    float px[8], pd[8];
#pragma unroll
    for (int u = 0; u < 8; u++) {
        const size_t o = base + (size_t)u * DI;
        px[u] = __half2float(g_xacth[o]);
        pd[u] = g_dt[o];
    }

    for (int t0 = 0; t0 < CLEN; t0 += 8) {
        float cx[8], cd[8];
#pragma unroll
        for (int u = 0; u < 8; u++) { cx[u] = px[u]; cd[u] = pd[u]; }
        if (t0 + 8 < CLEN) {
#pragma unroll
            for (int u = 0; u < 8; u++) {
                const size_t o = base + (size_t)(t0 + 8 + u) * DI;
                px[u] = __half2float(g_xacth[o]);
                pd[u] = g_dt[o];
            }
        }
#pragma unroll
        for (int u = 0; u < 8; u++) {
            const float dv  = cd[u];
            const float dtx = dv * cx[u];
            sdv += dv;
            h0 = ex2f(dv * a2[0]) * h0 + dtx;
            h1 = ex2f(dv * a2[1]) * h1 + dtx;
            h2 = ex2f(dv * a2[2]) * h2 + dtx;
            h3 = ex2f(dv * a2[3]) * h3 + dtx;
        }
    }

    const size_t idx = ((size_t)b * DI + c) * GCH + g;
    if (sg == 0) g_Sdv[idx] = sdv;
    float* ho = g_hout + idx * DS + sg * 4;
    ho[0] = h0; ho[1] = h1; ho[2] = h2; ho[3] = h3;
}

// ---------------- chunked scan: pass B (sequential combine) --------------------
__global__ void __launch_bounds__(256)
scanB_kernel()
{
    const int i = blockIdx.x * blockDim.x + threadIdx.x;
    if (i >= BB * DI * 4) return;
    const int sg = i & 3;
    const int c  = (i >> 2) & (DI - 1);
    const int b  = i >> 13;

    float a2[4];
#pragma unroll
    for (int s = 0; s < 4; s++) a2[s] = g_A2[c * DS + sg * 4 + s];

    float h[4] = {0.f, 0.f, 0.f, 0.f};
    const size_t row = ((size_t)b * DI + c) * GCH;
#pragma unroll
    for (int g = 0; g < GCH; g++) {
        const size_t idx = row + g;
        const float sdv = g_Sdv[idx];
        float* hi = g_hin  + idx * DS + sg * 4;
        const float* ho = g_hout + idx * DS + sg * 4;
#pragma unroll
        for (int s = 0; s < 4; s++) {
            hi[s] = h[s];
            h[s] = ex2f(a2[s] * sdv) * h[s] + ho[s];
        }
    }
}

// ---------------- chunked scan: pass C (recompute + gate) ----------------------
__global__ void __launch_bounds__(128)
scanC_kernel(const float* __restrict__ Dp)
{
    const int tid = threadIdx.x;
    const int sg  = tid & 3;
    const int cl  = tid >> 2;
    const int g   = blockIdx.x & (GCH - 1);
    const int cb  = (blockIdx.x >> 3) & 63;
    const int b   = blockIdx.x >> 9;
    const int c   = (cb << 5) + cl;

    float a2[4];
#pragma unroll
    for (int s = 0; s < 4; s++) a2[s] = g_A2[c * DS + sg * 4 + s];
    const float dpc = Dp[c];

    const size_t base = (size_t)b * LL * DI + (size_t)g * CLEN * DI + c;
    const size_t zoff = (size_t)b * LL * (2 * DI) + (size_t)g * CLEN * (2 * DI) + DI + c;

    const size_t idx = ((size_t)b * DI + c) * GCH + g;
    const float* hi = g_hin + idx * DS + sg * 4;
    float h0 = hi[0], h1 = hi[1], h2 = hi[2], h3 = hi[3];

    float px[8], pd[8];
#pragma unroll
    for (int u = 0; u < 8; u++) {
        const size_t o = base + (size_t)u * DI;
        px[u] = __half2float(g_xacth[o]);
        pd[u] = g_dt[o];
    }

    for (int t0 = 0; t0 < CLEN; t0 += 8) {
        float cx[8], cd[8];
#pragma unroll
        for (int u = 0; u < 8; u++) { cx[u] = px[u]; cd[u] = pd[u]; }
        if (t0 + 8 < CLEN) {
#pragma unroll
            for (int u = 0; u < 8; u++) {
                const size_t o = base + (size_t)(t0 + 8 + u) * DI;
                px[u] = __half2float(g_xacth[o]);
                pd[u] = g_dt[o];
            }
        }
#pragma unroll
        for (int u = 0; u < 8; u++) {
            const float xv  = cx[u];
            const float dv  = cd[u];
            const float dtx = dv * xv;
            h0 = ex2f(dv * a2[0]) * h0 + dtx;
            h1 = ex2f(dv * a2[1]) * h1 + dtx;
            h2 = ex2f(dv * a2[2]) * h2 + dtx;
            h3 = ex2f(dv * a2[3]) * h3 + dtx;
            float sum = (h0 + h1) + (h2 + h3);
            sum += __shfl_xor_sync(0xffffffffu, sum, 1);
            sum += __shfl_xor_sync(0xffffffffu, sum, 2);
            if (sg == 0) {
                const float zs = g_xz[zoff + (size_t)(t0 + u) * (2 * DI)];
                const float v  = (sum + dpc * xv) * zs;
                g_ygh[base + (size_t)(t0 + u) * DI] = __float2half_rn(v);
            }
        }
    }
}

// ---------------- launch -------------------------------------------------------
extern "C" void kernel_launch(void* const* d_in, const int* in_sizes, int n_in,
                              void* d_out, int out_size)
{
    (void)in_sizes; (void)n_in; (void)out_size;
    const float* x     = (const float*)d_in[0];
    const float* W_in  = (const float*)d_in[1];
    const float* cw    = (const float*)d_in[2];
    const float* cb    = (const float*)d_in[3];
    const float* A_log = (const float*)d_in[4];
    const float* Dp    = (const float*)d_in[5];
    const float* W_dt  = (const float*)d_in[6];
    const float* b_dt  = (const float*)d_in[7];
    const float* W_out = (const float*)d_in[8];
    float* out = (float*)d_out;

    float *xz, *dt;
    __half *xh, *winh, *wdth, *wouth, *xacth, *ygh;
    cudaGetSymbolAddress((void**)&xz,    g_xz);
    cudaGetSymbolAddress((void**)&dt,    g_dt);
    cudaGetSymbolAddress((void**)&xh,    g_xh);
    cudaGetSymbolAddress((void**)&winh,  g_Winh);
    cudaGetSymbolAddress((void**)&wdth,  g_Wdth);
    cudaGetSymbolAddress((void**)&wouth, g_Wouth);
    cudaGetSymbolAddress((void**)&xacth, g_xacth);
    cudaGetSymbolAddress((void**)&ygh,   g_ygh);

    cudaFuncSetAttribute(mma_gemm<2 * DI, DM, 1>,
                         cudaFuncAttributeMaxDynamicSharedMemorySize, GEMM_SMEM);
    cudaFuncSetAttribute(mma_gemm<DI, DI, 2>,
                         cudaFuncAttributeMaxDynamicSharedMemorySize, GEMM_SMEM);
    cudaFuncSetAttribute(mma_gemm<DM, DI, 0>,
                         cudaFuncAttributeMaxDynamicSharedMemorySize, GEMM_SMEM);

    // launches #1..#3 (profiler captures the 4th launch -> gemm1)
    prep_A2_kernel<<<(DI * DS + 255) / 256, 256>>>(A_log);
    cvt_kernel<<<(MM * DM / 4 + 255) / 256, 256>>>(x,    xh,   MM * DM / 4);
    cvt_kernel<<<(2 * DI * DM / 4 + 255) / 256, 256>>>(W_in, winh, 2 * DI * DM / 4);

    // #4: GEMM1: xz = x @ W_in^T  (silu fused on z half)   <-- profiled
    mma_gemm<2 * DI, DM, 1><<<dim3((2 * DI) / 128, MM / 128), 512, GEMM_SMEM>>>(
        xh, winh, xz, nullptr);

    cvt_kernel<<<(DI * DI / 4 + 255) / 256, 256>>>(W_dt, wdth, DI * DI / 4);
    conv_silu_kernel<<<(MM * DI + 255) / 256, 256>>>(cw, cb);

    // GEMM2: dt = softplus(x_act @ W_dt^T + b_dt)
    mma_gemm<DI, DI, 2><<<dim3(DI / 128, MM / 128), 512, GEMM_SMEM>>>(
        xacth, wdth, dt, b_dt);

    cvt_kernel<<<(DM * DI / 4 + 255) / 256, 256>>>(W_out, wouth, DM * DI / 4);

    // chunked scan
    scanA_kernel<<<BB * (DI / 32) * GCH, 128>>>();
    scanB_kernel<<<(BB * DI * 4 + 255) / 256, 256>>>();
    scanC_kernel<<<BB * (DI / 32) * GCH, 128>>>(Dp);

    // GEMM3: out = yg @ W_out^T
    mma_gemm<DM, DI, 0><<<dim3(DM / 128, MM / 128), 512, GEMM_SMEM>>>(
        ygh, wouth, out, nullptr);
}

// round 12
// speedup vs baseline: 1.3991x; 1.1322x over previous
#include <cuda_runtime.h>
#include <cuda_fp16.h>
#include <cstdint>

// Problem constants
#define DM   1024
#define DI   2048
#define DS   16
#define BB   2
#define LL   2048
#define MM   (BB*LL)         // 4096 tokens
#define GCH  32              // scan chunks
#define CLEN (LL/GCH)        // 64 steps per chunk

// ---------------- scratch (device globals) -----------------------------------
__device__ float g_A2 [DI * DS];               // -exp(A_log)*log2e

// fp16 operand / intermediate arrays
__device__ __half g_xh   [(size_t)MM * DM];
__device__ __half g_Winh [(size_t)2*DI * DM];
__device__ __half g_Wdth [(size_t)DI * DI];
__device__ __half g_Wouth[(size_t)DM * DI];
__device__ __half g_xph  [(size_t)MM * DI];    // x_proj (pre-conv)
__device__ __half g_zh   [(size_t)MM * DI];    // silu(z)
__device__ __half g_dth  [(size_t)MM * DI];    // softplus dt
__device__ __half g_xacth[(size_t)MM * DI];    // silu(conv(x_proj))
__device__ __half g_ygh  [(size_t)MM * DI];    // gated ssm output

// chunked-scan intermediates
__device__ float g_Sdv [(size_t)BB * DI * GCH];
__device__ float g_hout[(size_t)BB * DI * GCH * DS];
__device__ float g_hin [(size_t)BB * DI * GCH * DS];

// ---------------- scalar helpers ---------------------------------------------
__device__ __forceinline__ float ex2f(float x) {
    float y; asm("ex2.approx.ftz.f32 %0, %1;" : "=f"(y) : "f"(x)); return y;
}
__device__ __forceinline__ float siluf(float v) {
    return __fdividef(v, 1.0f + __expf(-v));
}
__device__ __forceinline__ float softplusf(float v) {
    return (v > 20.0f) ? v : log1pf(__expf(v));
}
__device__ __forceinline__ uint32_t smem_u32(const void* p) {
    uint32_t a;
    asm("{ .reg .u64 t; cvta.to.shared.u64 t, %1; cvt.u32.u64 %0, t; }" : "=r"(a) : "l"(p));
    return a;
}

// ---------------- PTX primitives (baseline ISA only) --------------------------
#define CP16(dst, src) \
    asm volatile("cp.async.cg.shared.global [%0], [%1], 16;" :: "r"(dst), "l"(src) : "memory")
#define CP_COMMIT() asm volatile("cp.async.commit_group;" ::: "memory")
#define CP_WAIT(n)  asm volatile("cp.async.wait_group %0;" :: "n"(n) : "memory")

#define LDSM4(r, addr) \
    asm volatile("ldmatrix.sync.aligned.m8n8.x4.shared.b16 {%0,%1,%2,%3}, [%4];" \
        : "=r"((r)[0]), "=r"((r)[1]), "=r"((r)[2]), "=r"((r)[3]) : "r"(addr))

#define MMA_F16(d, a, b0, b1) \
    asm volatile("mma.sync.aligned.m16n8k16.row.col.f32.f16.f16.f32 " \
        "{%0,%1,%2,%3}, {%4,%5,%6,%7}, {%8,%9}, {%0,%1,%2,%3};" \
        : "+f"((d)[0]), "+f"((d)[1]), "+f"((d)[2]), "+f"((d)[3]) \
        : "r"((a)[0]), "r"((a)[1]), "r"((a)[2]), "r"((a)[3]), "r"(b0), "r"(b1))

#define SWZ(off) ((off) ^ (((off) >> 3) & 0x70))

// ---------------- fp16 NT-GEMM via mma.sync ------------------------------------
// R9 tiling (proven optimum): 128x128 CTA tile, BK=64, 512 threads
// (16 warps: 4M x 4N, 32x32 warp tiles), 6-stage cp.async (192KB).
// EPI 0: fp32 C.  EPI 1: fp16 split -> x_proj | silu(z).  EPI 2: fp16 softplus.
static constexpr int STAGE_BYTES = 32768;                // Ah(16K) | Bh(16K)
static constexpr int NSTAGE      = 6;
static constexpr int GEMM_SMEM   = NSTAGE * STAGE_BYTES; // 192KB

template<int N, int K, int EPI>
__global__ void __launch_bounds__(512, 1)
mma_gemm(const __half* __restrict__ Ah, const __half* __restrict__ Bh,
         float* __restrict__ Cf, __half* __restrict__ Ch0,
         __half* __restrict__ Ch1, const float* __restrict__ bias)
{
    extern __shared__ __align__(1024) uint8_t smem[];
    const uint32_t sb = smem_u32(smem);
    const int tid = threadIdx.x, lane = tid & 31, wid = tid >> 5;
    const int wm = wid & 3, wn = wid >> 2;            // 4 x 4 warp grid
    const int bm = blockIdx.y * 128, bn = blockIdx.x * 128;
    constexpr int NC = K / 64;

    const int lrow = tid >> 2;                 // 0..127
    const int gp   = (tid & 3) * 2;            // 2 x 16B granules per array
    uint32_t dOff[2];
#pragma unroll
    for (int j = 0; j < 2; j++)
        dOff[j] = SWZ((uint32_t)lrow * 128 + (uint32_t)(gp + j) * 16);

    const __half* gAh = Ah + (size_t)(bm + lrow) * K;
    const __half* gBh = Bh + (size_t)(bn + lrow) * K;

    const int rA = (lane & 7) + ((lane >> 3) & 1) * 8;
    const int sA = ((lane >> 4) & 1) * 16;
    const uint32_t aOff = SWZ((uint32_t)(wm * 32 + rA) * 128 + sA);
    const int rB = (lane & 7) + ((lane >> 4) & 1) * 8;
    const int sB = ((lane >> 3) & 1) * 16;
    const uint32_t bOff = SWZ((uint32_t)(wn * 32 + rB) * 128 + sB);

    float acc[2][4][4];
#pragma unroll
    for (int i = 0; i < 2; i++)
#pragma unroll
        for (int j = 0; j < 4; j++)
#pragma unroll
            for (int q = 0; q < 4; q++) acc[i][j][q] = 0.f;

    auto issue = [&](int c) {
        const uint32_t s0 = sb + (uint32_t)(c % NSTAGE) * STAGE_BYTES;
        const int k0 = c * 64;
#pragma unroll
        for (int j = 0; j < 2; j++) {
            const int ke = k0 + (gp + j) * 8;
            CP16(s0 +         dOff[j], gAh + ke);
            CP16(s0 + 16384 + dOff[j], gBh + ke);
        }
        CP_COMMIT();
    };

#pragma unroll
    for (int s = 0; s < NSTAGE - 1 && s < NC; s++) issue(s);

    for (int c = 0; c < NC; c++) {
        if (c + NSTAGE - 1 < NC) { CP_WAIT(NSTAGE - 2); __syncthreads(); issue(c + NSTAGE - 1); }
        else                     { CP_WAIT(0); __syncthreads(); }

        const uint32_t s0 = sb + (uint32_t)(c % NSTAGE) * STAGE_BYTES;
        const uint32_t aB = s0 + aOff;
        const uint32_t bB = s0 + 16384 + bOff;
#pragma unroll
        for (int kk = 0; kk < 4; kk++) {
            const uint32_t kx = (uint32_t)kk * 32;
            uint32_t ah[2][4], bh[2][4];
#pragma unroll
            for (int mf = 0; mf < 2; mf++)
                LDSM4(ah[mf], (aB + (uint32_t)mf * 2048) ^ kx);
#pragma unroll
            for (int g = 0; g < 2; g++)
                LDSM4(bh[g], (bB + (uint32_t)g * 2048) ^ kx);
#pragma unroll
            for (int mf = 0; mf < 2; mf++)
#pragma unroll
                for (int g = 0; g < 2; g++)
#pragma unroll
                    for (int h = 0; h < 2; h++)
                        MMA_F16(acc[mf][g * 2 + h], ah[mf], bh[g][2 * h], bh[g][2 * h + 1]);
        }
    }

    // ---- epilogue ----
    const int qr = lane >> 2, qc = lane & 3;
#pragma unroll
    for (int mf = 0; mf < 2; mf++) {
#pragma unroll
        for (int p = 0; p < 2; p++) {
            const int row = bm + wm * 32 + mf * 16 + qr + p * 8;
#pragma unroll
            for (int nf = 0; nf < 4; nf++) {
                float vx = acc[mf][nf][2 * p];
                float vy = acc[mf][nf][2 * p + 1];
                const int col = bn + wn * 32 + nf * 8 + qc * 2;
                if (EPI == 0) {
                    float2 v; v.x = vx; v.y = vy;
                    *(float2*)(Cf + (size_t)row * N + col) = v;
                } else if (EPI == 1) {
                    const bool zs = (bn >= (N >> 1));
                    if (zs) { vx = siluf(vx); vy = siluf(vy); }
                    __half* dst = zs ? Ch1 : Ch0;
                    const int col2 = col - (zs ? (N >> 1) : 0);
                    *(__half2*)(dst + (size_t)row * (N >> 1) + col2) =
                        __floats2half2_rn(vx, vy);
                } else {  // EPI == 2
                    vx = softplusf(vx + bias[col]);
                    vy = softplusf(vy + bias[col + 1]);
                    *(__half2*)(Ch0 + (size_t)row * N + col) =
                        __floats2half2_rn(vx, vy);
                }
            }
        }
    }
}

// ---------------- fp32 -> fp16 convert (vectorized x4) -------------------------
__global__ void cvt_kernel(const float* __restrict__ in,
                           __half* __restrict__ oh, int n4)
{
    int i = blockIdx.x * blockDim.x + threadIdx.x;
    if (i >= n4) return;
    float4 v = ((const float4*)in)[i];
    ((__half2*)oh)[2 * i]     = __floats2half2_rn(v.x, v.y);
    ((__half2*)oh)[2 * i + 1] = __floats2half2_rn(v.z, v.w);
}

// ---------------- depthwise causal conv + SiLU (fp16 in/out) -------------------
__global__ void conv_silu_kernel(const float* __restrict__ cw,
                                 const float* __restrict__ cb)
{
    int idx = blockIdx.x * blockDim.x + threadIdx.x;
    if (idx >= MM * DI) return;
    const int c = idx & (DI - 1);
    const int m = idx >> 11;
    const int t = m & (LL - 1);

    const __half* p = g_xph + (size_t)m * DI + c;
    const float4 w = ((const float4*)cw)[c];
    float acc = cb[c] + w.w * __half2float(p[0]);
    if (t >= 1) acc += w.z * __half2float(p[-DI]);
    if (t >= 2) acc += w.y * __half2float(p[-2 * DI]);
    if (t >= 3) acc += w.x * __half2float(p[-3 * DI]);
    g_xacth[idx] = __float2half_rn(siluf(acc));
}

// ---------------- A2 = -exp(A_log) * log2(e) -----------------------------------
__global__ void prep_A2_kernel(const float* __restrict__ A_log)
{
    int i = blockIdx.x * blockDim.x + threadIdx.x;
    if (i < DI * DS) g_A2[i] = -expf(A_log[i]) * 1.4426950408889634f;
}

// ---------------- chunked scan: pass A -----------------------------------------
// 1 thread per (b, channel, chunk); 16 states in registers; coalesced fp16 loads.
#define SCAN_PF 4
__global__ void __launch_bounds__(128)
scanA_kernel()
{
    const int idx = blockIdx.x * 128 + threadIdx.x;
    const int c = idx & (DI - 1);
    const int g = (idx >> 11) & (GCH - 1);
    const int b = idx >> 16;

    float a2[DS];
#pragma unroll
    for (int s = 0; s < DS; s++) a2[s] = g_A2[c * DS + s];

    const size_t base = (size_t)b * LL * DI + (size_t)g * CLEN * DI + c;

    float h[DS];
#pragma unroll
    for (int s = 0; s < DS; s++) h[s] = 0.f;
    float sdv = 0.f;

    float px[SCAN_PF], pd[SCAN_PF];
#pragma unroll
    for (int u = 0; u < SCAN_PF; u++) {
        const size_t o = base + (size_t)u * DI;
        px[u] = __half2float(g_xacth[o]);
        pd[u] = __half2float(g_dth[o]);
    }

    for (int t0 = 0; t0 < CLEN; t0 += SCAN_PF) {
        float cx[SCAN_PF], cd[SCAN_PF];
#pragma unroll
        for (int u = 0; u < SCAN_PF; u++) { cx[u] = px[u]; cd[u] = pd[u]; }
        if (t0 + SCAN_PF < CLEN) {
#pragma unroll
            for (int u = 0; u < SCAN_PF; u++) {
                const size_t o = base + (size_t)(t0 + SCAN_PF + u) * DI;
                px[u] = __half2float(g_xacth[o]);
                pd[u] = __half2float(g_dth[o]);
            }
        }
#pragma unroll
        for (int u = 0; u < SCAN_PF; u++) {
            const float dv  = cd[u];
            const float dtx = dv * cx[u];
            sdv += dv;
#pragma unroll
            for (int s = 0; s < DS; s++)
                h[s] = ex2f(dv * a2[s]) * h[s] + dtx;
        }
    }

    const size_t oidx = ((size_t)b * DI + c) * GCH + g;
    g_Sdv[oidx] = sdv;
    float4* ho = (float4*)(g_hout + oidx * DS);
#pragma unroll
    for (int q = 0; q < 4; q++) {
        float4 v; v.x = h[4*q]; v.y = h[4*q+1]; v.z = h[4*q+2]; v.w = h[4*q+3];
        ho[q] = v;
    }
}

// ---------------- chunked scan: pass B (sequential combine) --------------------
__global__ void __launch_bounds__(256)
scanB_kernel()
{
    const int i = blockIdx.x * blockDim.x + threadIdx.x;
    if (i >= BB * DI) return;
    const int c = i & (DI - 1);

    float a2[DS];
#pragma unroll
    for (int s = 0; s < DS; s++) a2[s] = g_A2[c * DS + s];

    float h[DS];
#pragma unroll
    for (int s = 0; s < DS; s++) h[s] = 0.f;

    const size_t row = (size_t)i * GCH;
#pragma unroll
    for (int g = 0; g < GCH; g++) {
        const size_t oidx = row + g;
        const float sdv = g_Sdv[oidx];
        float4* hi = (float4*)(g_hin + oidx * DS);
        const float4* ho = (const float4*)(g_hout + oidx * DS);
#pragma unroll
        for (int q = 0; q < 4; q++) {
            float4 hv; hv.x = h[4*q]; hv.y = h[4*q+1]; hv.z = h[4*q+2]; hv.w = h[4*q+3];
            hi[q] = hv;
            float4 hov = ho[q];
            h[4*q+0] = ex2f(a2[4*q+0] * sdv) * h[4*q+0] + hov.x;
            h[4*q+1] = ex2f(a2[4*q+1] * sdv) * h[4*q+1] + hov.y;
            h[4*q+2] = ex2f(a2[4*q+2] * sdv) * h[4*q+2] + hov.z;
            h[4*q+3] = ex2f(a2[4*q+3] * sdv) * h[4*q+3] + hov.w;
        }
    }
}

// ---------------- chunked scan: pass C (recompute + gate, fp16 out) ------------
__global__ void __launch_bounds__(128)
scanC_kernel(const float* __restrict__ Dp)
{
    const int idx = blockIdx.x * 128 + threadIdx.x;
    const int c = idx & (DI - 1);
    const int g = (idx >> 11) & (GCH - 1);
    const int b = idx >> 16;

    float a2[DS];
#pragma unroll
    for (int s = 0; s < DS; s++) a2[s] = g_A2[c * DS + s];
    const float dpc = Dp[c];

    const size_t base = (size_t)b * LL * DI + (size_t)g * CLEN * DI + c;
    const size_t oidx = ((size_t)b * DI + c) * GCH + g;

    float h[DS];
    {
        const float4* hi = (const float4*)(g_hin + oidx * DS);
#pragma unroll
        for (int q = 0; q < 4; q++) {
            float4 v = hi[q];
            h[4*q] = v.x; h[4*q+1] = v.y; h[4*q+2] = v.z; h[4*q+3] = v.w;
        }
    }

    float px[SCAN_PF], pd[SCAN_PF], pz[SCAN_PF];
#pragma unroll
    for (int u = 0; u < SCAN_PF; u++) {
        const size_t o = base + (size_t)u * DI;
        px[u] = __half2float(g_xacth[o]);
        pd[u] = __half2float(g_dth[o]);
        pz[u] = __half2float(g_zh[o]);
    }

    for (int t0 = 0; t0 < CLEN; t0 += SCAN_PF) {
        float cx[SCAN_PF], cd[SCAN_PF], cz[SCAN_PF];
#pragma unroll
        for (int u = 0; u < SCAN_PF; u++) { cx[u] = px[u]; cd[u] = pd[u]; cz[u] = pz[u]; }
        if (t0 + SCAN_PF < CLEN) {
#pragma unroll
            for (int u = 0; u < SCAN_PF; u++) {
                const size_t o = base + (size_t)(t0 + SCAN_PF + u) * DI;
                px[u] = __half2float(g_xacth[o]);
                pd[u] = __half2float(g_dth[o]);
                pz[u] = __half2float(g_zh[o]);
            }
        }
#pragma unroll
        for (int u = 0; u < SCAN_PF; u++) {
            const float xv  = cx[u];
            const float dv  = cd[u];
            const float dtx = dv * xv;
#pragma unroll
            for (int s = 0; s < DS; s++)
                h[s] = ex2f(dv * a2[s]) * h[s] + dtx;
            // tree sum of 16 states
            float s0 = (h[0] + h[1]) + (h[2] + h[3]);
            float s1 = (h[4] + h[5]) + (h[6] + h[7]);
            float s2 = (h[8] + h[9]) + (h[10] + h[11]);
            float s3 = (h[12] + h[13]) + (h[14] + h[15]);
            const float sum = (s0 + s1) + (s2 + s3);
            g_ygh[base + (size_t)(t0 + u) * DI] =
                __float2half_rn((sum + dpc * xv) * cz[u]);
        }
    }
}

// ---------------- launch -------------------------------------------------------
extern "C" void kernel_launch(void* const* d_in, const int* in_sizes, int n_in,
                              void* d_out, int out_size)
{
    (void)in_sizes; (void)n_in; (void)out_size;
    const float* x     = (const float*)d_in[0];
    const float* W_in  = (const float*)d_in[1];
    const float* cw    = (const float*)d_in[2];
    const float* cb    = (const float*)d_in[3];
    const float* A_log = (const float*)d_in[4];
    const float* Dp    = (const float*)d_in[5];
    const float* W_dt  = (const float*)d_in[6];
    const float* b_dt  = (const float*)d_in[7];
    const float* W_out = (const float*)d_in[8];
    float* out = (float*)d_out;

    __half *xh, *winh, *wdth, *wouth, *xph, *zh, *dth, *xacth, *ygh;
    cudaGetSymbolAddress((void**)&xh,    g_xh);
    cudaGetSymbolAddress((void**)&winh,  g_Winh);
    cudaGetSymbolAddress((void**)&wdth,  g_Wdth);
    cudaGetSymbolAddress((void**)&wouth, g_Wouth);
    cudaGetSymbolAddress((void**)&xph,   g_xph);
    cudaGetSymbolAddress((void**)&zh,    g_zh);
    cudaGetSymbolAddress((void**)&dth,   g_dth);
    cudaGetSymbolAddress((void**)&xacth, g_xacth);
    cudaGetSymbolAddress((void**)&ygh,   g_ygh);

    cudaFuncSetAttribute(mma_gemm<2 * DI, DM, 1>,
                         cudaFuncAttributeMaxDynamicSharedMemorySize, GEMM_SMEM);
    cudaFuncSetAttribute(mma_gemm<DI, DI, 2>,
                         cudaFuncAttributeMaxDynamicSharedMemorySize, GEMM_SMEM);
    cudaFuncSetAttribute(mma_gemm<DM, DI, 0>,
                         cudaFuncAttributeMaxDynamicSharedMemorySize, GEMM_SMEM);

    // launches #1..#3 (profiler captures the 4th launch -> gemm1)
    prep_A2_kernel<<<(DI * DS + 255) / 256, 256>>>(A_log);
    cvt_kernel<<<(MM * DM / 4 + 255) / 256, 256>>>(x,    xh,   MM * DM / 4);
    cvt_kernel<<<(2 * DI * DM / 4 + 255) / 256, 256>>>(W_in, winh, 2 * DI * DM / 4);

    // #4: GEMM1: x_proj | silu(z), both fp16                 <-- profiled
    mma_gemm<2 * DI, DM, 1><<<dim3((2 * DI) / 128, MM / 128), 512, GEMM_SMEM>>>(
        xh, winh, nullptr, xph, zh, nullptr);

    cvt_kernel<<<(DI * DI / 4 + 255) / 256, 256>>>(W_dt, wdth, DI * DI / 4);
    conv_silu_kernel<<<(MM * DI + 255) / 256, 256>>>(cw, cb);

    // GEMM2: dt = softplus(x_act @ W_dt^T + b_dt), fp16 out
    mma_gemm<DI, DI, 2><<<dim3(DI / 128, MM / 128), 512, GEMM_SMEM>>>(
        xacth, wdth, nullptr, dth, nullptr, b_dt);

    cvt_kernel<<<(DM * DI / 4 + 255) / 256, 256>>>(W_out, wouth, DM * DI / 4);

    // chunked scan (GCH=32, 1 thread per channel-chunk)
    scanA_kernel<<<BB * DI * GCH / 128, 128>>>();
    scanB_kernel<<<(BB * DI + 255) / 256, 256>>>();
    scanC_kernel<<<BB * DI * GCH / 128, 128>>>(Dp);

    // GEMM3: out = yg @ W_out^T (fp32 out)
    mma_gemm<DM, DI, 0><<<dim3(DM / 128, MM / 128), 512, GEMM_SMEM>>>(
        ygh, wouth, out, nullptr, nullptr, nullptr);
}

// round 13
// speedup vs baseline: 1.4529x; 1.0385x over previous
#include <cuda_runtime.h>
#include <cuda_fp16.h>
#include <cstdint>

// Problem constants
#define DM   1024
#define DI   2048
#define DS   16
#define BB   2
#define LL   2048
#define MM   (BB*LL)         // 4096 tokens
#define GCH  32              // scan chunks
#define CLEN (LL/GCH)        // 64 steps per chunk

// ---------------- scratch (device globals) -----------------------------------
__device__ float g_A2 [DI * DS];               // -exp(A_log)*log2e

// fp16 operand / intermediate arrays
__device__ __half g_xh   [(size_t)MM * DM];
__device__ __half g_Winh [(size_t)2*DI * DM];
__device__ __half g_Wdth [(size_t)DI * DI];
__device__ __half g_Wouth[(size_t)DM * DI];
__device__ __half g_xph  [(size_t)MM * DI];    // x_proj (pre-conv)
__device__ __half g_zh   [(size_t)MM * DI];    // silu(z)
__device__ __half g_dth  [(size_t)MM * DI];    // softplus dt
__device__ __half g_xacth[(size_t)MM * DI];    // silu(conv(x_proj))
__device__ __half g_ygh  [(size_t)MM * DI];    // gated ssm output

// chunked-scan intermediates
__device__ float g_Sdv [(size_t)BB * DI * GCH];
__device__ float g_hout[(size_t)BB * DI * GCH * DS];
__device__ float g_hin [(size_t)BB * DI * GCH * DS];

// ---------------- scalar helpers ---------------------------------------------
__device__ __forceinline__ float ex2f(float x) {
    float y; asm("ex2.approx.ftz.f32 %0, %1;" : "=f"(y) : "f"(x)); return y;
}
__device__ __forceinline__ float siluf(float v) {
    return __fdividef(v, 1.0f + __expf(-v));
}
__device__ __forceinline__ float softplusf(float v) {
    return (v > 20.0f) ? v : log1pf(__expf(v));
}
__device__ __forceinline__ uint32_t smem_u32(const void* p) {
    uint32_t a;
    asm("{ .reg .u64 t; cvta.to.shared.u64 t, %1; cvt.u32.u64 %0, t; }" : "=r"(a) : "l"(p));
    return a;
}

// ---------------- PTX primitives (baseline ISA only) --------------------------
#define CP16(dst, src) \
    asm volatile("cp.async.cg.shared.global [%0], [%1], 16;" :: "r"(dst), "l"(src) : "memory")
#define CP_COMMIT() asm volatile("cp.async.commit_group;" ::: "memory")
#define CP_WAIT(n)  asm volatile("cp.async.wait_group %0;" :: "n"(n) : "memory")

#define LDSM4(r, addr) \
    asm volatile("ldmatrix.sync.aligned.m8n8.x4.shared.b16 {%0,%1,%2,%3}, [%4];" \
        : "=r"((r)[0]), "=r"((r)[1]), "=r"((r)[2]), "=r"((r)[3]) : "r"(addr))

#define MMA_F16(d, a, b0, b1) \
    asm volatile("mma.sync.aligned.m16n8k16.row.col.f32.f16.f16.f32 " \
        "{%0,%1,%2,%3}, {%4,%5,%6,%7}, {%8,%9}, {%0,%1,%2,%3};" \
        : "+f"((d)[0]), "+f"((d)[1]), "+f"((d)[2]), "+f"((d)[3]) \
        : "r"((a)[0]), "r"((a)[1]), "r"((a)[2]), "r"((a)[3]), "r"(b0), "r"(b1))

#define SWZ(off) ((off) ^ (((off) >> 3) & 0x70))

// ---------------- fp16 NT-GEMM via mma.sync ------------------------------------
// R9 tiling (proven): 128x128 CTA tile, BK=64, 512 threads (16 warps: 4M x 4N,
// 32x32 warp tiles), 6-stage cp.async (192KB).
// NEW: pair-chunk mainloop — one CP_WAIT + barrier per TWO chunks (8 syncs,
// not 16), letting warps drift to overlap LDSM with MMA across chunks.
static constexpr int STAGE_BYTES = 32768;                // Ah(16K) | Bh(16K)
static constexpr int NSTAGE      = 6;
static constexpr int GEMM_SMEM   = NSTAGE * STAGE_BYTES; // 192KB

template<int N, int K, int EPI>
__global__ void __launch_bounds__(512, 1)
mma_gemm(const __half* __restrict__ Ah, const __half* __restrict__ Bh,
         float* __restrict__ Cf, __half* __restrict__ Ch0,
         __half* __restrict__ Ch1, const float* __restrict__ bias)
{
    extern __shared__ __align__(1024) uint8_t smem[];
    const uint32_t sb = smem_u32(smem);
    const int tid = threadIdx.x, lane = tid & 31, wid = tid >> 5;
    const int wm = wid & 3, wn = wid >> 2;            // 4 x 4 warp grid
    const int bm = blockIdx.y * 128, bn = blockIdx.x * 128;
    constexpr int NC = K / 64;

    const int lrow = tid >> 2;                 // 0..127
    const int gp   = (tid & 3) * 2;            // 2 x 16B granules per array
    uint32_t dOff[2];
#pragma unroll
    for (int j = 0; j < 2; j++)
        dOff[j] = SWZ((uint32_t)lrow * 128 + (uint32_t)(gp + j) * 16);

    const __half* gAh = Ah + (size_t)(bm + lrow) * K;
    const __half* gBh = Bh + (size_t)(bn + lrow) * K;

    const int rA = (lane & 7) + ((lane >> 3) & 1) * 8;
    const int sA = ((lane >> 4) & 1) * 16;
    const uint32_t aOff = SWZ((uint32_t)(wm * 32 + rA) * 128 + sA);
    const int rB = (lane & 7) + ((lane >> 4) & 1) * 8;
    const int sB = ((lane >> 3) & 1) * 16;
    const uint32_t bOff = SWZ((uint32_t)(wn * 32 + rB) * 128 + sB);

    float acc[2][4][4];
#pragma unroll
    for (int i = 0; i < 2; i++)
#pragma unroll
        for (int j = 0; j < 4; j++)
#pragma unroll
            for (int q = 0; q < 4; q++) acc[i][j][q] = 0.f;

    auto issue = [&](int c) {
        const uint32_t s0 = sb + (uint32_t)(c % NSTAGE) * STAGE_BYTES;
        const int k0 = c * 64;
#pragma unroll
        for (int j = 0; j < 2; j++) {
            const int ke = k0 + (gp + j) * 8;
            CP16(s0 +         dOff[j], gAh + ke);
            CP16(s0 + 16384 + dOff[j], gBh + ke);
        }
        CP_COMMIT();
    };

    auto compute = [&](int c) {
        const uint32_t s0 = sb + (uint32_t)(c % NSTAGE) * STAGE_BYTES;
        const uint32_t aB = s0 + aOff;
        const uint32_t bB = s0 + 16384 + bOff;
#pragma unroll
        for (int kk = 0; kk < 4; kk++) {
            const uint32_t kx = (uint32_t)kk * 32;
            uint32_t ah[2][4], bh[2][4];
#pragma unroll
            for (int mf = 0; mf < 2; mf++)
                LDSM4(ah[mf], (aB + (uint32_t)mf * 2048) ^ kx);
#pragma unroll
            for (int g = 0; g < 2; g++)
                LDSM4(bh[g], (bB + (uint32_t)g * 2048) ^ kx);
#pragma unroll
            for (int mf = 0; mf < 2; mf++)
#pragma unroll
                for (int g = 0; g < 2; g++)
#pragma unroll
                    for (int h = 0; h < 2; h++)
                        MMA_F16(acc[mf][g * 2 + h], ah[mf], bh[g][2 * h], bh[g][2 * h + 1]);
        }
    };

    // prologue: 4 chunks in flight
#pragma unroll
    for (int s = 0; s < 4 && s < NC; s++) issue(s);

    // pair-chunk mainloop: one wait+barrier per 2 chunks
    for (int p = 0; p < NC / 2; p++) {
        const int c0 = 2 * p;
        if (c0 + 4 < NC) {
            CP_WAIT(2);          // chunks c0, c0+1 complete
            __syncthreads();
            issue(c0 + 4);
            issue(c0 + 5);
        } else {
            CP_WAIT(0);
            __syncthreads();
        }
        compute(c0);
        compute(c0 + 1);
    }

    // ---- epilogue ----
    const int qr = lane >> 2, qc = lane & 3;
#pragma unroll
    for (int mf = 0; mf < 2; mf++) {
#pragma unroll
        for (int p = 0; p < 2; p++) {
            const int row = bm + wm * 32 + mf * 16 + qr + p * 8;
#pragma unroll
            for (int nf = 0; nf < 4; nf++) {
                float vx = acc[mf][nf][2 * p];
                float vy = acc[mf][nf][2 * p + 1];
                const int col = bn + wn * 32 + nf * 8 + qc * 2;
                if (EPI == 0) {
                    float2 v; v.x = vx; v.y = vy;
                    *(float2*)(Cf + (size_t)row * N + col) = v;
                } else if (EPI == 1) {
                    const bool zs = (bn >= (N >> 1));
                    if (zs) { vx = siluf(vx); vy = siluf(vy); }
                    __half* dst = zs ? Ch1 : Ch0;
                    const int col2 = col - (zs ? (N >> 1) : 0);
                    *(__half2*)(dst + (size_t)row * (N >> 1) + col2) =
                        __floats2half2_rn(vx, vy);
                } else {  // EPI == 2
                    vx = softplusf(vx + bias[col]);
                    vy = softplusf(vy + bias[col + 1]);
                    *(__half2*)(Ch0 + (size_t)row * N + col) =
                        __floats2half2_rn(vx, vy);
                }
            }
        }
    }
}

// ---------------- fp32 -> fp16 converts ----------------------------------------
__global__ void cvt_kernel(const float* __restrict__ in,
                           __half* __restrict__ oh, int n4)
{
    int i = blockIdx.x * blockDim.x + threadIdx.x;
    if (i >= n4) return;
    float4 v = ((const float4*)in)[i];
    ((__half2*)oh)[2 * i]     = __floats2half2_rn(v.x, v.y);
    ((__half2*)oh)[2 * i + 1] = __floats2half2_rn(v.z, v.w);
}

// fused convert of the three weight matrices (one launch)
__global__ void cvtW_kernel(const float* __restrict__ w1, __half* __restrict__ o1, int n1,
                            const float* __restrict__ w2, __half* __restrict__ o2, int n2,
                            const float* __restrict__ w3, __half* __restrict__ o3, int n3)
{
    int i = blockIdx.x * blockDim.x + threadIdx.x;
    const float* in; __half* oh;
    if (i < n1)           { in = w1; oh = o1; }
    else if (i < n1 + n2) { in = w2; oh = o2; i -= n1; }
    else if (i < n1 + n2 + n3) { in = w3; oh = o3; i -= n1 + n2; }
    else return;
    float4 v = ((const float4*)in)[i];
    ((__half2*)oh)[2 * i]     = __floats2half2_rn(v.x, v.y);
    ((__half2*)oh)[2 * i + 1] = __floats2half2_rn(v.z, v.w);
}

// ---------------- depthwise causal conv + SiLU (fp16 in/out) -------------------
__global__ void conv_silu_kernel(const float* __restrict__ cw,
                                 const float* __restrict__ cb)
{
    int idx = blockIdx.x * blockDim.x + threadIdx.x;
    if (idx >= MM * DI) return;
    const int c = idx & (DI - 1);
    const int m = idx >> 11;
    const int t = m & (LL - 1);

    const __half* p = g_xph + (size_t)m * DI + c;
    const float4 w = ((const float4*)cw)[c];
    float acc = cb[c] + w.w * __half2float(p[0]);
    if (t >= 1) acc += w.z * __half2float(p[-DI]);
    if (t >= 2) acc += w.y * __half2float(p[-2 * DI]);
    if (t >= 3) acc += w.x * __half2float(p[-3 * DI]);
    g_xacth[idx] = __float2half_rn(siluf(acc));
}

// ---------------- A2 = -exp(A_log) * log2(e) -----------------------------------
__global__ void prep_A2_kernel(const float* __restrict__ A_log)
{
    int i = blockIdx.x * blockDim.x + threadIdx.x;
    if (i < DI * DS) g_A2[i] = -expf(A_log[i]) * 1.4426950408889634f;
}

// ---------------- chunked scan: pass A -----------------------------------------
#define SCAN_PF 4
__global__ void __launch_bounds__(128)
scanA_kernel()
{
    const int idx = blockIdx.x * 128 + threadIdx.x;
    const int c = idx & (DI - 1);
    const int g = (idx >> 11) & (GCH - 1);
    const int b = idx >> 16;

    float a2[DS];
#pragma unroll
    for (int s = 0; s < DS; s++) a2[s] = g_A2[c * DS + s];

    const size_t base = (size_t)b * LL * DI + (size_t)g * CLEN * DI + c;

    float h[DS];
#pragma unroll
    for (int s = 0; s < DS; s++) h[s] = 0.f;
    float sdv = 0.f;

    float px[SCAN_PF], pd[SCAN_PF];
#pragma unroll
    for (int u = 0; u < SCAN_PF; u++) {
        const size_t o = base + (size_t)u * DI;
        px[u] = __half2float(g_xacth[o]);
        pd[u] = __half2float(g_dth[o]);
    }

    for (int t0 = 0; t0 < CLEN; t0 += SCAN_PF) {
        float cx[SCAN_PF], cd[SCAN_PF];
#pragma unroll
        for (int u = 0; u < SCAN_PF; u++) { cx[u] = px[u]; cd[u] = pd[u]; }
        if (t0 + SCAN_PF < CLEN) {
#pragma unroll
            for (int u = 0; u < SCAN_PF; u++) {
                const size_t o = base + (size_t)(t0 + SCAN_PF + u) * DI;
                px[u] = __half2float(g_xacth[o]);
                pd[u] = __half2float(g_dth[o]);
            }
        }
#pragma unroll
        for (int u = 0; u < SCAN_PF; u++) {
            const float dv  = cd[u];
            const float dtx = dv * cx[u];
            sdv += dv;
#pragma unroll
            for (int s = 0; s < DS; s++)
                h[s] = ex2f(dv * a2[s]) * h[s] + dtx;
        }
    }

    const size_t oidx = ((size_t)b * DI + c) * GCH + g;
    g_Sdv[oidx] = sdv;
    float4* ho = (float4*)(g_hout + oidx * DS);
#pragma unroll
    for (int q = 0; q < 4; q++) {
        float4 v; v.x = h[4*q]; v.y = h[4*q+1]; v.z = h[4*q+2]; v.w = h[4*q+3];
        ho[q] = v;
    }
}

// ---------------- chunked scan: pass B (sequential combine) --------------------
__global__ void __launch_bounds__(256)
scanB_kernel()
{
    const int i = blockIdx.x * blockDim.x + threadIdx.x;
    if (i >= BB * DI) return;
    const int c = i & (DI - 1);

    float a2[DS];
#pragma unroll
    for (int s = 0; s < DS; s++) a2[s] = g_A2[c * DS + s];

    float h[DS];
#pragma unroll
    for (int s = 0; s < DS; s++) h[s] = 0.f;

    const size_t row = (size_t)i * GCH;
#pragma unroll
    for (int g = 0; g < GCH; g++) {
        const size_t oidx = row + g;
        const float sdv = g_Sdv[oidx];
        float4* hi = (float4*)(g_hin + oidx * DS);
        const float4* ho = (const float4*)(g_hout + oidx * DS);
#pragma unroll
        for (int q = 0; q < 4; q++) {
            float4 hv; hv.x = h[4*q]; hv.y = h[4*q+1]; hv.z = h[4*q+2]; hv.w = h[4*q+3];
            hi[q] = hv;
            float4 hov = ho[q];
            h[4*q+0] = ex2f(a2[4*q+0] * sdv) * h[4*q+0] + hov.x;
            h[4*q+1] = ex2f(a2[4*q+1] * sdv) * h[4*q+1] + hov.y;
            h[4*q+2] = ex2f(a2[4*q+2] * sdv) * h[4*q+2] + hov.z;
            h[4*q+3] = ex2f(a2[4*q+3] * sdv) * h[4*q+3] + hov.w;
        }
    }
}

// ---------------- chunked scan: pass C (recompute + gate, fp16 out) ------------
__global__ void __launch_bounds__(128)
scanC_kernel(const float* __restrict__ Dp)
{
    const int idx = blockIdx.x * 128 + threadIdx.x;
    const int c = idx & (DI - 1);
    const int g = (idx >> 11) & (GCH - 1);
    const int b = idx >> 16;

    float a2[DS];
#pragma unroll
    for (int s = 0; s < DS; s++) a2[s] = g_A2[c * DS + s];
    const float dpc = Dp[c];

    const size_t base = (size_t)b * LL * DI + (size_t)g * CLEN * DI + c;
    const size_t oidx = ((size_t)b * DI + c) * GCH + g;

    float h[DS];
    {
        const float4* hi = (const float4*)(g_hin + oidx * DS);
#pragma unroll
        for (int q = 0; q < 4; q++) {
            float4 v = hi[q];
            h[4*q] = v.x; h[4*q+1] = v.y; h[4*q+2] = v.z; h[4*q+3] = v.w;
        }
    }

    float px[SCAN_PF], pd[SCAN_PF], pz[SCAN_PF];
#pragma unroll
    for (int u = 0; u < SCAN_PF; u++) {
        const size_t o = base + (size_t)u * DI;
        px[u] = __half2float(g_xacth[o]);
        pd[u] = __half2float(g_dth[o]);
        pz[u] = __half2float(g_zh[o]);
    }

    for (int t0 = 0; t0 < CLEN; t0 += SCAN_PF) {
        float cx[SCAN_PF], cd[SCAN_PF], cz[SCAN_PF];
#pragma unroll
        for (int u = 0; u < SCAN_PF; u++) { cx[u] = px[u]; cd[u] = pd[u]; cz[u] = pz[u]; }
        if (t0 + SCAN_PF < CLEN) {
#pragma unroll
            for (int u = 0; u < SCAN_PF; u++) {
                const size_t o = base + (size_t)(t0 + SCAN_PF + u) * DI;
                px[u] = __half2float(g_xacth[o]);
                pd[u] = __half2float(g_dth[o]);
                pz[u] = __half2float(g_zh[o]);
            }
        }
#pragma unroll
        for (int u = 0; u < SCAN_PF; u++) {
            const float xv  = cx[u];
            const float dv  = cd[u];
            const float dtx = dv * xv;
#pragma unroll
            for (int s = 0; s < DS; s++)
                h[s] = ex2f(dv * a2[s]) * h[s] + dtx;
            float s0 = (h[0] + h[1]) + (h[2] + h[3]);
            float s1 = (h[4] + h[5]) + (h[6] + h[7]);
            float s2 = (h[8] + h[9]) + (h[10] + h[11]);
            float s3 = (h[12] + h[13]) + (h[14] + h[15]);
            const float sum = (s0 + s1) + (s2 + s3);
            g_ygh[base + (size_t)(t0 + u) * DI] =
                __float2half_rn((sum + dpc * xv) * cz[u]);
        }
    }
}

// ---------------- launch -------------------------------------------------------
extern "C" void kernel_launch(void* const* d_in, const int* in_sizes, int n_in,
                              void* d_out, int out_size)
{
    (void)in_sizes; (void)n_in; (void)out_size;
    const float* x     = (const float*)d_in[0];
    const float* W_in  = (const float*)d_in[1];
    const float* cw    = (const float*)d_in[2];
    const float* cb    = (const float*)d_in[3];
    const float* A_log = (const float*)d_in[4];
    const float* Dp    = (const float*)d_in[5];
    const float* W_dt  = (const float*)d_in[6];
    const float* b_dt  = (const float*)d_in[7];
    const float* W_out = (const float*)d_in[8];
    float* out = (float*)d_out;

    __half *xh, *winh, *wdth, *wouth, *xph, *zh, *dth, *xacth, *ygh;
    cudaGetSymbolAddress((void**)&xh,    g_xh);
    cudaGetSymbolAddress((void**)&winh,  g_Winh);
    cudaGetSymbolAddress((void**)&wdth,  g_Wdth);
    cudaGetSymbolAddress((void**)&wouth, g_Wouth);
    cudaGetSymbolAddress((void**)&xph,   g_xph);
    cudaGetSymbolAddress((void**)&zh,    g_zh);
    cudaGetSymbolAddress((void**)&dth,   g_dth);
    cudaGetSymbolAddress((void**)&xacth, g_xacth);
    cudaGetSymbolAddress((void**)&ygh,   g_ygh);

    cudaFuncSetAttribute(mma_gemm<2 * DI, DM, 1>,
                         cudaFuncAttributeMaxDynamicSharedMemorySize, GEMM_SMEM);
    cudaFuncSetAttribute(mma_gemm<DI, DI, 2>,
                         cudaFuncAttributeMaxDynamicSharedMemorySize, GEMM_SMEM);
    cudaFuncSetAttribute(mma_gemm<DM, DI, 0>,
                         cudaFuncAttributeMaxDynamicSharedMemorySize, GEMM_SMEM);

    constexpr int N1 = 2 * DI * DM / 4, N2 = DI * DI / 4, N3 = DM * DI / 4;

    // launches #1..#3 (profiler captures the 4th launch -> gemm1)
    prep_A2_kernel<<<(DI * DS + 255) / 256, 256>>>(A_log);
    cvtW_kernel<<<(N1 + N2 + N3 + 255) / 256, 256>>>(W_in, winh, N1,
                                                     W_dt, wdth, N2,
                                                     W_out, wouth, N3);
    cvt_kernel<<<(MM * DM / 4 + 255) / 256, 256>>>(x, xh, MM * DM / 4);

    // #4: GEMM1: x_proj | silu(z), both fp16                 <-- profiled
    mma_gemm<2 * DI, DM, 1><<<dim3((2 * DI) / 128, MM / 128), 512, GEMM_SMEM>>>(
        xh, winh, nullptr, xph, zh, nullptr);

    conv_silu_kernel<<<(MM * DI + 255) / 256, 256>>>(cw, cb);

    // GEMM2: dt = softplus(x_act @ W_dt^T + b_dt), fp16 out
    mma_gemm<DI, DI, 2><<<dim3(DI / 128, MM / 128), 512, GEMM_SMEM>>>(
        xacth, wdth, nullptr, dth, nullptr, b_dt);

    // chunked scan (GCH=32, 1 thread per channel-chunk)
    scanA_kernel<<<BB * DI * GCH / 128, 128>>>();
    scanB_kernel<<<(BB * DI + 255) / 256, 256>>>();
    scanC_kernel<<<BB * DI * GCH / 128, 128>>>(Dp);

    // GEMM3: out = yg @ W_out^T (fp32 out)
    mma_gemm<DM, DI, 0><<<dim3(DM / 128, MM / 128), 512, GEMM_SMEM>>>(
        ygh, wouth, out, nullptr, nullptr, nullptr);
}

// round 14
// speedup vs baseline: 1.7326x; 1.1925x over previous
#include <cuda_runtime.h>
#include <cuda_fp16.h>
#include <cstdint>

// Problem constants
#define DM   1024
#define DI   2048
#define DS   16
#define BB   2
#define LL   2048
#define MM   (BB*LL)         // 4096 tokens
#define GCH  32              // scan chunks
#define CLEN (LL/GCH)        // 64 steps per chunk
#define SCH  16              // channels per fused-scan CTA

// ---------------- scratch (device globals) -----------------------------------
__device__ float g_A2 [DI * DS];               // -exp(A_log)*log2e

// fp16 operand / intermediate arrays
__device__ __half g_xh   [(size_t)MM * DM];
__device__ __half g_Winh [(size_t)2*DI * DM];
__device__ __half g_Wdth [(size_t)DI * DI];
__device__ __half g_Wouth[(size_t)DM * DI];
__device__ __half g_xph  [(size_t)MM * DI];    // x_proj (pre-conv)
__device__ __half g_zh   [(size_t)MM * DI];    // silu(z)
__device__ __half g_dth  [(size_t)MM * DI];    // softplus dt
__device__ __half g_xacth[(size_t)MM * DI];    // silu(conv(x_proj))
__device__ __half g_ygh  [(size_t)MM * DI];    // gated ssm output

// ---------------- scalar helpers ---------------------------------------------
__device__ __forceinline__ float ex2f(float x) {
    float y; asm("ex2.approx.ftz.f32 %0, %1;" : "=f"(y) : "f"(x)); return y;
}
__device__ __forceinline__ float siluf(float v) {
    return __fdividef(v, 1.0f + __expf(-v));
}
__device__ __forceinline__ float softplusf(float v) {
    return (v > 20.0f) ? v : log1pf(__expf(v));
}
__device__ __forceinline__ uint32_t smem_u32(const void* p) {
    uint32_t a;
    asm("{ .reg .u64 t; cvta.to.shared.u64 t, %1; cvt.u32.u64 %0, t; }" : "=r"(a) : "l"(p));
    return a;
}

// ---------------- PTX primitives (baseline ISA only) --------------------------
#define CP16(dst, src) \
    asm volatile("cp.async.cg.shared.global [%0], [%1], 16;" :: "r"(dst), "l"(src) : "memory")
#define CP_COMMIT() asm volatile("cp.async.commit_group;" ::: "memory")
#define CP_WAIT(n)  asm volatile("cp.async.wait_group %0;" :: "n"(n) : "memory")

#define LDSM4(r, addr) \
    asm volatile("ldmatrix.sync.aligned.m8n8.x4.shared.b16 {%0,%1,%2,%3}, [%4];" \
        : "=r"((r)[0]), "=r"((r)[1]), "=r"((r)[2]), "=r"((r)[3]) : "r"(addr))

#define MMA_F16(d, a, b0, b1) \
    asm volatile("mma.sync.aligned.m16n8k16.row.col.f32.f16.f16.f32 " \
        "{%0,%1,%2,%3}, {%4,%5,%6,%7}, {%8,%9}, {%0,%1,%2,%3};" \
        : "+f"((d)[0]), "+f"((d)[1]), "+f"((d)[2]), "+f"((d)[3]) \
        : "r"((a)[0]), "r"((a)[1]), "r"((a)[2]), "r"((a)[3]), "r"(b0), "r"(b1))

#define SWZ(off) ((off) ^ (((off) >> 3) & 0x70))

// ---------------- fp16 NT-GEMM via mma.sync (R13 config, frozen) ---------------
static constexpr int STAGE_BYTES = 32768;                // Ah(16K) | Bh(16K)
static constexpr int NSTAGE      = 6;
static constexpr int GEMM_SMEM   = NSTAGE * STAGE_BYTES; // 192KB

template<int N, int K, int EPI>
__global__ void __launch_bounds__(512, 1)
mma_gemm(const __half* __restrict__ Ah, const __half* __restrict__ Bh,
         float* __restrict__ Cf, __half* __restrict__ Ch0,
         __half* __restrict__ Ch1, const float* __restrict__ bias)
{
    extern __shared__ __align__(1024) uint8_t smem[];
    const uint32_t sb = smem_u32(smem);
    const int tid = threadIdx.x, lane = tid & 31, wid = tid >> 5;
    const int wm = wid & 3, wn = wid >> 2;            // 4 x 4 warp grid
    const int bm = blockIdx.y * 128, bn = blockIdx.x * 128;
    constexpr int NC = K / 64;

    const int lrow = tid >> 2;                 // 0..127
    const int gp   = (tid & 3) * 2;            // 2 x 16B granules per array
    uint32_t dOff[2];
#pragma unroll
    for (int j = 0; j < 2; j++)
        dOff[j] = SWZ((uint32_t)lrow * 128 + (uint32_t)(gp + j) * 16);

    const __half* gAh = Ah + (size_t)(bm + lrow) * K;
    const __half* gBh = Bh + (size_t)(bn + lrow) * K;

    const int rA = (lane & 7) + ((lane >> 3) & 1) * 8;
    const int sA = ((lane >> 4) & 1) * 16;
    const uint32_t aOff = SWZ((uint32_t)(wm * 32 + rA) * 128 + sA);
    const int rB = (lane & 7) + ((lane >> 4) & 1) * 8;
    const int sB = ((lane >> 3) & 1) * 16;
    const uint32_t bOff = SWZ((uint32_t)(wn * 32 + rB) * 128 + sB);

    float acc[2][4][4];
#pragma unroll
    for (int i = 0; i < 2; i++)
#pragma unroll
        for (int j = 0; j < 4; j++)
#pragma unroll
            for (int q = 0; q < 4; q++) acc[i][j][q] = 0.f;

    auto issue = [&](int c) {
        const uint32_t s0 = sb + (uint32_t)(c % NSTAGE) * STAGE_BYTES;
        const int k0 = c * 64;
#pragma unroll
        for (int j = 0; j < 2; j++) {
            const int ke = k0 + (gp + j) * 8;
            CP16(s0 +         dOff[j], gAh + ke);
            CP16(s0 + 16384 + dOff[j], gBh + ke);
        }
        CP_COMMIT();
    };

    auto compute = [&](int c) {
        const uint32_t s0 = sb + (uint32_t)(c % NSTAGE) * STAGE_BYTES;
        const uint32_t aB = s0 + aOff;
        const uint32_t bB = s0 + 16384 + bOff;
#pragma unroll
        for (int kk = 0; kk < 4; kk++) {
            const uint32_t kx = (uint32_t)kk * 32;
            uint32_t ah[2][4], bh[2][4];
#pragma unroll
            for (int mf = 0; mf < 2; mf++)
                LDSM4(ah[mf], (aB + (uint32_t)mf * 2048) ^ kx);
#pragma unroll
            for (int g = 0; g < 2; g++)
                LDSM4(bh[g], (bB + (uint32_t)g * 2048) ^ kx);
#pragma unroll
            for (int mf = 0; mf < 2; mf++)
#pragma unroll
                for (int g = 0; g < 2; g++)
#pragma unroll
                    for (int h = 0; h < 2; h++)
                        MMA_F16(acc[mf][g * 2 + h], ah[mf], bh[g][2 * h], bh[g][2 * h + 1]);
        }
    };

#pragma unroll
    for (int s = 0; s < 4 && s < NC; s++) issue(s);

    for (int p = 0; p < NC / 2; p++) {
        const int c0 = 2 * p;
        if (c0 + 4 < NC) {
            CP_WAIT(2);
            __syncthreads();
            issue(c0 + 4);
            issue(c0 + 5);
        } else {
            CP_WAIT(0);
            __syncthreads();
        }
        compute(c0);
        compute(c0 + 1);
    }

    // ---- epilogue ----
    const int qr = lane >> 2, qc = lane & 3;
#pragma unroll
    for (int mf = 0; mf < 2; mf++) {
#pragma unroll
        for (int p = 0; p < 2; p++) {
            const int row = bm + wm * 32 + mf * 16 + qr + p * 8;
#pragma unroll
            for (int nf = 0; nf < 4; nf++) {
                float vx = acc[mf][nf][2 * p];
                float vy = acc[mf][nf][2 * p + 1];
                const int col = bn + wn * 32 + nf * 8 + qc * 2;
                if (EPI == 0) {
                    float2 v; v.x = vx; v.y = vy;
                    *(float2*)(Cf + (size_t)row * N + col) = v;
                } else if (EPI == 1) {
                    const bool zs = (bn >= (N >> 1));
                    if (zs) { vx = siluf(vx); vy = siluf(vy); }
                    __half* dst = zs ? Ch1 : Ch0;
                    const int col2 = col - (zs ? (N >> 1) : 0);
                    *(__half2*)(dst + (size_t)row * (N >> 1) + col2) =
                        __floats2half2_rn(vx, vy);
                } else {  // EPI == 2
                    vx = softplusf(vx + bias[col]);
                    vy = softplusf(vy + bias[col + 1]);
                    *(__half2*)(Ch0 + (size_t)row * N + col) =
                        __floats2half2_rn(vx, vy);
                }
            }
        }
    }
}

// ---------------- fp32 -> fp16 converts ----------------------------------------
__global__ void cvt_kernel(const float* __restrict__ in,
                           __half* __restrict__ oh, int n4)
{
    int i = blockIdx.x * blockDim.x + threadIdx.x;
    if (i >= n4) return;
    float4 v = ((const float4*)in)[i];
    ((__half2*)oh)[2 * i]     = __floats2half2_rn(v.x, v.y);
    ((__half2*)oh)[2 * i + 1] = __floats2half2_rn(v.z, v.w);
}

__global__ void cvtW_kernel(const float* __restrict__ w1, __half* __restrict__ o1, int n1,
                            const float* __restrict__ w2, __half* __restrict__ o2, int n2,
                            const float* __restrict__ w3, __half* __restrict__ o3, int n3)
{
    int i = blockIdx.x * blockDim.x + threadIdx.x;
    const float* in; __half* oh;
    if (i < n1)           { in = w1; oh = o1; }
    else if (i < n1 + n2) { in = w2; oh = o2; i -= n1; }
    else if (i < n1 + n2 + n3) { in = w3; oh = o3; i -= n1 + n2; }
    else return;
    float4 v = ((const float4*)in)[i];
    ((__half2*)oh)[2 * i]     = __floats2half2_rn(v.x, v.y);
    ((__half2*)oh)[2 * i + 1] = __floats2half2_rn(v.z, v.w);
}

// ---------------- depthwise causal conv + SiLU: 8 tokens per thread ------------
__global__ void conv_silu_kernel(const float* __restrict__ cw,
                                 const float* __restrict__ cb)
{
    const int idx = blockIdx.x * blockDim.x + threadIdx.x;
    if (idx >= (MM / 8) * DI) return;
    const int c  = idx & (DI - 1);
    const int tg = idx >> 11;                  // token-group (8 tokens)
    const int m0 = tg * 8;
    const int t0 = m0 & (LL - 1);              // position in sequence

    const float4 w = ((const float4*)cw)[c];
    const float bias = cb[c];

    const __half* p = g_xph + (size_t)m0 * DI + c;
    float v[11];
#pragma unroll
    for (int j = 0; j < 3; j++)
        v[j] = (t0 + j >= 3) ? __half2float(p[(int)(j - 3) * DI]) : 0.f;
#pragma unroll
    for (int j = 0; j < 8; j++)
        v[3 + j] = __half2float(p[j * DI]);

    __half* o = g_xacth + (size_t)m0 * DI + c;
#pragma unroll
    for (int u = 0; u < 8; u++) {
        float acc = bias + w.x * v[u] + w.y * v[u + 1] + w.z * v[u + 2] + w.w * v[u + 3];
        o[u * DI] = __float2half_rn(siluf(acc));
    }
}

// ---------------- A2 = -exp(A_log) * log2(e) -----------------------------------
__global__ void prep_A2_kernel(const float* __restrict__ A_log)
{
    int i = blockIdx.x * blockDim.x + threadIdx.x;
    if (i < DI * DS) g_A2[i] = -expf(A_log[i]) * 1.4426950408889634f;
}

// ---------------- fused chunked scan (A + combine + C in one kernel) -----------
// CTA: 16 channels x 64 (batch,chunk) lanes = 1024 threads. Grid = DI/16 = 128.
// Phase A: per-lane chunk scan (h_in=0) -> (h_out, sum dt) in SMEM (pad 17).
// Phase B: 32 threads run the 32-chunk sequential combine per (b,ch) in SMEM.
// Phase C: per-lane rescan with correct h_in; gate with silu(z); fp16 out.
#define SCAN_PF 4
static constexpr int SCAN_SMEM = (64 * SCH * 17 + 64 * SCH) * 4;  // 73,728 B

__global__ void __launch_bounds__(1024, 1)
scan_fused_kernel(const float* __restrict__ Dp)
{
    extern __shared__ float sm[];
    float* s_hio = sm;                         // [64*SCH][17]
    float* s_sdv = sm + 64 * SCH * 17;         // [64*SCH]

    const int tid = threadIdx.x;
    const int ch  = tid & (SCH - 1);
    const int bg  = tid >> 4;                  // 0..63
    const int b   = bg >> 5;
    const int g   = bg & (GCH - 1);
    const int c   = blockIdx.x * SCH + ch;
    const int li  = bg * SCH + ch;             // lane index in SMEM

    float a2[DS];
#pragma unroll
    for (int s = 0; s < DS; s++) a2[s] = g_A2[c * DS + s];

    const size_t base = (size_t)b * LL * DI + (size_t)g * CLEN * DI + c;

    // ---- Phase A ----
    {
        float h[DS];
#pragma unroll
        for (int s = 0; s < DS; s++) h[s] = 0.f;
        float sdv = 0.f;

        float px[SCAN_PF], pd[SCAN_PF];
#pragma unroll
        for (int u = 0; u < SCAN_PF; u++) {
            const size_t o = base + (size_t)u * DI;
            px[u] = __half2float(g_xacth[o]);
            pd[u] = __half2float(g_dth[o]);
        }
        for (int t0 = 0; t0 < CLEN; t0 += SCAN_PF) {
            float cx[SCAN_PF], cd[SCAN_PF];
#pragma unroll
            for (int u = 0; u < SCAN_PF; u++) { cx[u] = px[u]; cd[u] = pd[u]; }
            if (t0 + SCAN_PF < CLEN) {
#pragma unroll
                for (int u = 0; u < SCAN_PF; u++) {
                    const size_t o = base + (size_t)(t0 + SCAN_PF + u) * DI;
                    px[u] = __half2float(g_xacth[o]);
                    pd[u] = __half2float(g_dth[o]);
                }
            }
#pragma unroll
            for (int u = 0; u < SCAN_PF; u++) {
                const float dv  = cd[u];
                const float dtx = dv * cx[u];
                sdv += dv;
#pragma unroll
                for (int s = 0; s < DS; s++)
                    h[s] = ex2f(dv * a2[s]) * h[s] + dtx;
            }
        }
        s_sdv[li] = sdv;
#pragma unroll
        for (int s = 0; s < DS; s++) s_hio[li * 17 + s] = h[s];
    }
    __syncthreads();

    // ---- Phase B: sequential combine, 32 threads (2 b x 16 ch) ----
    if (tid < 2 * SCH) {
        const int ch2 = tid & (SCH - 1);
        const int b2  = tid >> 4;
        const int c2  = blockIdx.x * SCH + ch2;
        float a22[DS];
#pragma unroll
        for (int s = 0; s < DS; s++) a22[s] = g_A2[c2 * DS + s];
        float h[DS];
#pragma unroll
        for (int s = 0; s < DS; s++) h[s] = 0.f;
        for (int g2 = 0; g2 < GCH; g2++) {
            const int li2 = (b2 * GCH + g2) * SCH + ch2;
            const float sd = s_sdv[li2];
#pragma unroll
            for (int s = 0; s < DS; s++) {
                const float ho = s_hio[li2 * 17 + s];
                s_hio[li2 * 17 + s] = h[s];          // h_in for phase C
                h[s] = ex2f(a22[s] * sd) * h[s] + ho;
            }
        }
    }
    __syncthreads();

    // ---- Phase C ----
    {
        float h[DS];
#pragma unroll
        for (int s = 0; s < DS; s++) h[s] = s_hio[li * 17 + s];
        const float dpc = Dp[c];

        float px[SCAN_PF], pd[SCAN_PF], pz[SCAN_PF];
#pragma unroll
        for (int u = 0; u < SCAN_PF; u++) {
            const size_t o = base + (size_t)u * DI;
            px[u] = __half2float(g_xacth[o]);
            pd[u] = __half2float(g_dth[o]);
            pz[u] = __half2float(g_zh[o]);
        }
        for (int t0 = 0; t0 < CLEN; t0 += SCAN_PF) {
            float cx[SCAN_PF], cd[SCAN_PF], cz[SCAN_PF];
#pragma unroll
            for (int u = 0; u < SCAN_PF; u++) { cx[u] = px[u]; cd[u] = pd[u]; cz[u] = pz[u]; }
            if (t0 + SCAN_PF < CLEN) {
#pragma unroll
                for (int u = 0; u < SCAN_PF; u++) {
                    const size_t o = base + (size_t)(t0 + SCAN_PF + u) * DI;
                    px[u] = __half2float(g_xacth[o]);
                    pd[u] = __half2float(g_dth[o]);
                    pz[u] = __half2float(g_zh[o]);
                }
            }
#pragma unroll
            for (int u = 0; u < SCAN_PF; u++) {
                const float xv  = cx[u];
                const float dv  = cd[u];
                const float dtx = dv * xv;
#pragma unroll
                for (int s = 0; s < DS; s++)
                    h[s] = ex2f(dv * a2[s]) * h[s] + dtx;
                float s0 = (h[0] + h[1]) + (h[2] + h[3]);
                float s1 = (h[4] + h[5]) + (h[6] + h[7]);
                float s2 = (h[8] + h[9]) + (h[10] + h[11]);
                float s3 = (h[12] + h[13]) + (h[14] + h[15]);
                const float sum = (s0 + s1) + (s2 + s3);
                g_ygh[base + (size_t)(t0 + u) * DI] =
                    __float2half_rn((sum + dpc * xv) * cz[u]);
            }
        }
    }
}

// ---------------- launch -------------------------------------------------------
extern "C" void kernel_launch(void* const* d_in, const int* in_sizes, int n_in,
                              void* d_out, int out_size)
{
    (void)in_sizes; (void)n_in; (void)out_size;
    const float* x     = (const float*)d_in[0];
    const float* W_in  = (const float*)d_in[1];
    const float* cw    = (const float*)d_in[2];
    const float* cb    = (const float*)d_in[3];
    const float* A_log = (const float*)d_in[4];
    const float* Dp    = (const float*)d_in[5];
    const float* W_dt  = (const float*)d_in[6];
    const float* b_dt  = (const float*)d_in[7];
    const float* W_out = (const float*)d_in[8];
    float* out = (float*)d_out;

    __half *xh, *winh, *wdth, *wouth, *xph, *zh, *dth, *xacth, *ygh;
    cudaGetSymbolAddress((void**)&xh,    g_xh);
    cudaGetSymbolAddress((void**)&winh,  g_Winh);
    cudaGetSymbolAddress((void**)&wdth,  g_Wdth);
    cudaGetSymbolAddress((void**)&wouth, g_Wouth);
    cudaGetSymbolAddress((void**)&xph,   g_xph);
    cudaGetSymbolAddress((void**)&zh,    g_zh);
    cudaGetSymbolAddress((void**)&dth,   g_dth);
    cudaGetSymbolAddress((void**)&xacth, g_xacth);
    cudaGetSymbolAddress((void**)&ygh,   g_ygh);

    cudaFuncSetAttribute(mma_gemm<2 * DI, DM, 1>,
                         cudaFuncAttributeMaxDynamicSharedMemorySize, GEMM_SMEM);
    cudaFuncSetAttribute(mma_gemm<DI, DI, 2>,
                         cudaFuncAttributeMaxDynamicSharedMemorySize, GEMM_SMEM);
    cudaFuncSetAttribute(mma_gemm<DM, DI, 0>,
                         cudaFuncAttributeMaxDynamicSharedMemorySize, GEMM_SMEM);
    cudaFuncSetAttribute(scan_fused_kernel,
                         cudaFuncAttributeMaxDynamicSharedMemorySize, SCAN_SMEM);

    constexpr int N1 = 2 * DI * DM / 4, N2 = DI * DI / 4, N3 = DM * DI / 4;

    // launches #1..#3 (profiler captures the 4th launch -> gemm1)
    prep_A2_kernel<<<(DI * DS + 255) / 256, 256>>>(A_log);
    cvtW_kernel<<<(N1 + N2 + N3 + 255) / 256, 256>>>(W_in, winh, N1,
                                                     W_dt, wdth, N2,
                                                     W_out, wouth, N3);
    cvt_kernel<<<(MM * DM / 4 + 255) / 256, 256>>>(x, xh, MM * DM / 4);

    // #4: GEMM1: x_proj | silu(z), both fp16                 <-- profiled
    mma_gemm<2 * DI, DM, 1><<<dim3((2 * DI) / 128, MM / 128), 512, GEMM_SMEM>>>(
        xh, winh, nullptr, xph, zh, nullptr);

    // conv: 8 tokens per thread
    conv_silu_kernel<<<((MM / 8) * DI + 255) / 256, 256>>>(cw, cb);

    // GEMM2: dt = softplus(x_act @ W_dt^T + b_dt), fp16 out
    mma_gemm<DI, DI, 2><<<dim3(DI / 128, MM / 128), 512, GEMM_SMEM>>>(
        xacth, wdth, nullptr, dth, nullptr, b_dt);

    // fused chunked scan (A + combine + C)
    scan_fused_kernel<<<DI / SCH, 1024, SCAN_SMEM>>>(Dp);

    // GEMM3: out = yg @ W_out^T (fp32 out)
    mma_gemm<DM, DI, 0><<<dim3(DM / 128, MM / 128), 512, GEMM_SMEM>>>(
        ygh, wouth, out, nullptr, nullptr, nullptr);
}

// round 16
// speedup vs baseline: 1.9650x; 1.1341x over previous
#include <cuda_runtime.h>
#include <cuda_fp16.h>
#include <cstdint>

// Problem constants
#define DM   1024
#define DI   2048
#define DS   16
#define BB   2
#define LL   2048
#define MM   (BB*LL)         // 4096 tokens
#define GCH  32              // scan chunks
#define CLEN (LL/GCH)        // 64 steps per chunk
#define SCH  16              // channels per fused-scan CTA

// ---------------- scratch (device globals) -----------------------------------
__device__ float g_A2 [DI * DS];               // -exp(A_log)*log2e

// fp16 operand / intermediate arrays
__device__ __half g_xh   [(size_t)MM * DM];
__device__ __half g_Winh [(size_t)2*DI * DM];
__device__ __half g_Wdth [(size_t)DI * DI];
__device__ __half g_Wouth[(size_t)DM * DI];
__device__ __half g_xph  [(size_t)MM * DI];    // x_proj (pre-conv)
__device__ __half g_zh   [(size_t)MM * DI];    // silu(z)
__device__ __half g_dth  [(size_t)MM * DI];    // softplus dt
__device__ __half g_xacth[(size_t)MM * DI];    // silu(conv(x_proj))
__device__ __half g_ygh  [(size_t)MM * DI];    // gated ssm output

// ---------------- scalar helpers ---------------------------------------------
__device__ __forceinline__ float ex2f(float x) {
    float y; asm("ex2.approx.ftz.f32 %0, %1;" : "=f"(y) : "f"(x)); return y;
}
__device__ __forceinline__ float siluf(float v) {
    return __fdividef(v, 1.0f + __expf(-v));
}
__device__ __forceinline__ float softplusf(float v) {
    return (v > 20.0f) ? v : log1pf(__expf(v));
}
__device__ __forceinline__ uint32_t smem_u32(const void* p) {
    uint32_t a;
    asm("{ .reg .u64 t; cvta.to.shared.u64 t, %1; cvt.u32.u64 %0, t; }" : "=r"(a) : "l"(p));
    return a;
}

// ---------------- PTX primitives (baseline ISA only) --------------------------
#define CP16(dst, src) \
    asm volatile("cp.async.cg.shared.global [%0], [%1], 16;" :: "r"(dst), "l"(src) : "memory")
#define CP_COMMIT() asm volatile("cp.async.commit_group;" ::: "memory")
#define CP_WAIT(n)  asm volatile("cp.async.wait_group %0;" :: "n"(n) : "memory")

#define LDSM4(r, addr) \
    asm volatile("ldmatrix.sync.aligned.m8n8.x4.shared.b16 {%0,%1,%2,%3}, [%4];" \
        : "=r"((r)[0]), "=r"((r)[1]), "=r"((r)[2]), "=r"((r)[3]) : "r"(addr))

#define MMA_F16(d, a, b0, b1) \
    asm volatile("mma.sync.aligned.m16n8k16.row.col.f32.f16.f16.f32 " \
        "{%0,%1,%2,%3}, {%4,%5,%6,%7}, {%8,%9}, {%0,%1,%2,%3};" \
        : "+f"((d)[0]), "+f"((d)[1]), "+f"((d)[2]), "+f"((d)[3]) \
        : "r"((a)[0]), "r"((a)[1]), "r"((a)[2]), "r"((a)[3]), "r"(b0), "r"(b1))

#define SWZ(off) ((off) ^ (((off) >> 3) & 0x70))

// ---------------- fp16 NT-GEMM via mma.sync ------------------------------------
// CTA tile 128(M) x 256(N), 1024 threads (32 warps: 4M x 8N, warp tile 32x32),
// BK=64, 4-stage cp.async (192KB).
// RACE FIX vs R15: with 4 stages, issue(c0+4) targets stage c0%4 — must come
// AFTER compute(c0)/compute(c0+1) + barrier, not before.
static constexpr int TN          = 256;
static constexpr int STAGE_BYTES = 49152;              // A(16K) | B(32K)
static constexpr int NSTAGE      = 4;
static constexpr int GEMM_SMEM   = NSTAGE * STAGE_BYTES; // 192KB

template<int N, int K, int EPI>
__global__ void __launch_bounds__(1024, 1)
mma_gemm(const __half* __restrict__ Ah, const __half* __restrict__ Bh,
         float* __restrict__ Cf, __half* __restrict__ Ch0,
         __half* __restrict__ Ch1, const float* __restrict__ bias)
{
    extern __shared__ __align__(1024) uint8_t smem[];
    const uint32_t sb = smem_u32(smem);
    const int tid = threadIdx.x, lane = tid & 31, wid = tid >> 5;
    const int wm = wid & 3, wn = wid >> 2;            // 4M x 8N warp grid
    const int bm = blockIdx.y * 128, bn = blockIdx.x * TN;
    constexpr int NC = K / 64;

    // ---- cp.async mapping: per stage 384 rows x 128B (A 128 | B 256) ---------
    uint32_t dOff[3];
    const __half* gptr[3];
#pragma unroll
    for (int j = 0; j < 3; j++) {
        const int gg  = tid + j * 1024;
        const int row = gg >> 3;
        const int col = gg & 7;
        const bool isB = row >= 128;
        const int lrow = isB ? row - 128 : row;
        dOff[j] = (isB ? 16384u : 0u) + SWZ((uint32_t)lrow * 128 + (uint32_t)col * 16);
        gptr[j] = (isB ? Bh + (size_t)(bn + lrow) * K
                       : Ah + (size_t)(bm + lrow) * K) + col * 8;
    }

    // ---- ldmatrix lane offsets ----
    const int rA = (lane & 7) + ((lane >> 3) & 1) * 8;
    const int sA = ((lane >> 4) & 1) * 16;
    const uint32_t aOff = SWZ((uint32_t)(wm * 32 + rA) * 128 + sA);
    const int rB = (lane & 7) + ((lane >> 4) & 1) * 8;
    const int sB = ((lane >> 3) & 1) * 16;
    const uint32_t bOff = SWZ((uint32_t)(wn * 32 + rB) * 128 + sB);

    float acc[2][4][4];
#pragma unroll
    for (int i = 0; i < 2; i++)
#pragma unroll
        for (int j = 0; j < 4; j++)
#pragma unroll
            for (int q = 0; q < 4; q++) acc[i][j][q] = 0.f;

    auto issue = [&](int c) {
        const uint32_t s0 = sb + (uint32_t)(c % NSTAGE) * STAGE_BYTES;
        const int k0 = c * 64;
#pragma unroll
        for (int j = 0; j < 3; j++)
            CP16(s0 + dOff[j], gptr[j] + k0);
        CP_COMMIT();
    };

    auto compute = [&](int c) {
        const uint32_t s0 = sb + (uint32_t)(c % NSTAGE) * STAGE_BYTES;
        const uint32_t aB = s0 + aOff;
        const uint32_t bB = s0 + 16384u + bOff;
#pragma unroll
        for (int kk = 0; kk < 4; kk++) {
            const uint32_t kx = (uint32_t)kk * 32;
            uint32_t ah[2][4], bh[2][4];
#pragma unroll
            for (int mf = 0; mf < 2; mf++)
                LDSM4(ah[mf], (aB + (uint32_t)mf * 2048) ^ kx);
#pragma unroll
            for (int g = 0; g < 2; g++)
                LDSM4(bh[g], (bB + (uint32_t)g * 2048) ^ kx);
#pragma unroll
            for (int mf = 0; mf < 2; mf++)
#pragma unroll
                for (int g = 0; g < 2; g++)
#pragma unroll
                    for (int h = 0; h < 2; h++)
                        MMA_F16(acc[mf][g * 2 + h], ah[mf], bh[g][2 * h], bh[g][2 * h + 1]);
        }
    };

    // prologue: fill all 4 stages
#pragma unroll
    for (int s = 0; s < NSTAGE && s < NC; s++) issue(s);

    // pair-chunk mainloop (compute-then-issue ordering: stage-safe with 4 stages)
    for (int p = 0; p < NC / 2; p++) {
        const int c0 = 2 * p;
        if (c0 + 4 < NC) CP_WAIT(2);    // chunks c0, c0+1 landed
        else             CP_WAIT(0);
        __syncthreads();
        compute(c0);
        compute(c0 + 1);
        if (c0 + 4 < NC) {
            __syncthreads();            // all warps done reading stages c0%4,(c0+1)%4
            issue(c0 + 4);
            issue(c0 + 5);
        }
    }

    // ---- epilogue ----
    const int qr = lane >> 2, qc = lane & 3;
#pragma unroll
    for (int mf = 0; mf < 2; mf++) {
#pragma unroll
        for (int p = 0; p < 2; p++) {
            const int row = bm + wm * 32 + mf * 16 + qr + p * 8;
#pragma unroll
            for (int nf = 0; nf < 4; nf++) {
                float vx = acc[mf][nf][2 * p];
                float vy = acc[mf][nf][2 * p + 1];
                const int col = bn + wn * 32 + nf * 8 + qc * 2;
                if (EPI == 0) {
                    float2 v; v.x = vx; v.y = vy;
                    *(float2*)(Cf + (size_t)row * N + col) = v;
                } else if (EPI == 1) {
                    const bool zs = (bn >= (N >> 1));
                    if (zs) { vx = siluf(vx); vy = siluf(vy); }
                    __half* dst = zs ? Ch1 : Ch0;
                    const int col2 = col - (zs ? (N >> 1) : 0);
                    *(__half2*)(dst + (size_t)row * (N >> 1) + col2) =
                        __floats2half2_rn(vx, vy);
                } else {  // EPI == 2
                    vx = softplusf(vx + bias[col]);
                    vy = softplusf(vy + bias[col + 1]);
                    *(__half2*)(Ch0 + (size_t)row * N + col) =
                        __floats2half2_rn(vx, vy);
                }
            }
        }
    }
}

// ---------------- fp32 -> fp16 converts ----------------------------------------
__global__ void cvt_kernel(const float* __restrict__ in,
                           __half* __restrict__ oh, int n4)
{
    int i = blockIdx.x * blockDim.x + threadIdx.x;
    if (i >= n4) return;
    float4 v = ((const float4*)in)[i];
    ((__half2*)oh)[2 * i]     = __floats2half2_rn(v.x, v.y);
    ((__half2*)oh)[2 * i + 1] = __floats2half2_rn(v.z, v.w);
}

__global__ void cvtW_kernel(const float* __restrict__ w1, __half* __restrict__ o1, int n1,
                            const float* __restrict__ w2, __half* __restrict__ o2, int n2,
                            const float* __restrict__ w3, __half* __restrict__ o3, int n3)
{
    int i = blockIdx.x * blockDim.x + threadIdx.x;
    const float* in; __half* oh;
    if (i < n1)           { in = w1; oh = o1; }
    else if (i < n1 + n2) { in = w2; oh = o2; i -= n1; }
    else if (i < n1 + n2 + n3) { in = w3; oh = o3; i -= n1 + n2; }
    else return;
    float4 v = ((const float4*)in)[i];
    ((__half2*)oh)[2 * i]     = __floats2half2_rn(v.x, v.y);
    ((__half2*)oh)[2 * i + 1] = __floats2half2_rn(v.z, v.w);
}

// ---------------- depthwise causal conv + SiLU: 8 tokens per thread ------------
__global__ void conv_silu_kernel(const float* __restrict__ cw,
                                 const float* __restrict__ cb)
{
    const int idx = blockIdx.x * blockDim.x + threadIdx.x;
    if (idx >= (MM / 8) * DI) return;
    const int c  = idx & (DI - 1);
    const int tg = idx >> 11;                  // token-group (8 tokens)
    const int m0 = tg * 8;
    const int t0 = m0 & (LL - 1);              // position in sequence

    const float4 w = ((const float4*)cw)[c];
    const float bias = cb[c];

    const __half* p = g_xph + (size_t)m0 * DI + c;
    float v[11];
#pragma unroll
    for (int j = 0; j < 3; j++)
        v[j] = (t0 + j >= 3) ? __half2float(p[(int)(j - 3) * DI]) : 0.f;
#pragma unroll
    for (int j = 0; j < 8; j++)
        v[3 + j] = __half2float(p[j * DI]);

    __half* o = g_xacth + (size_t)m0 * DI + c;
#pragma unroll
    for (int u = 0; u < 8; u++) {
        float acc = bias + w.x * v[u] + w.y * v[u + 1] + w.z * v[u + 2] + w.w * v[u + 3];
        o[u * DI] = __float2half_rn(siluf(acc));
    }
}

// ---------------- A2 = -exp(A_log) * log2(e) -----------------------------------
__global__ void prep_A2_kernel(const float* __restrict__ A_log)
{
    int i = blockIdx.x * blockDim.x + threadIdx.x;
    if (i < DI * DS) g_A2[i] = -expf(A_log[i]) * 1.4426950408889634f;
}

// ---------------- fused chunked scan (A + combine + C) -------------------------
#define SCAN_PF 4
static constexpr int SCAN_SMEM = (64 * SCH * 17 + 64 * SCH) * 4;  // 73,728 B

__global__ void __launch_bounds__(1024, 1)
scan_fused_kernel(const float* __restrict__ Dp)
{
    extern __shared__ float sm[];
    float* s_hio = sm;                         // [64*SCH][17]
    float* s_sdv = sm + 64 * SCH * 17;         // [64*SCH]

    const int tid = threadIdx.x;
    const int ch  = tid & (SCH - 1);
    const int bg  = tid >> 4;                  // 0..63
    const int b   = bg >> 5;
    const int g   = bg & (GCH - 1);
    const int c   = blockIdx.x * SCH + ch;
    const int li  = bg * SCH + ch;

    float a2[DS];
#pragma unroll
    for (int s = 0; s < DS; s++) a2[s] = g_A2[c * DS + s];

    const size_t base = (size_t)b * LL * DI + (size_t)g * CLEN * DI + c;

    // ---- Phase A ----
    {
        float h[DS];
#pragma unroll
        for (int s = 0; s < DS; s++) h[s] = 0.f;
        float sdv = 0.f;

        float px[SCAN_PF], pd[SCAN_PF];
#pragma unroll
        for (int u = 0; u < SCAN_PF; u++) {
            const size_t o = base + (size_t)u * DI;
            px[u] = __half2float(g_xacth[o]);
            pd[u] = __half2float(g_dth[o]);
        }
        for (int t0 = 0; t0 < CLEN; t0 += SCAN_PF) {
            float cx[SCAN_PF], cd[SCAN_PF];
#pragma unroll
            for (int u = 0; u < SCAN_PF; u++) { cx[u] = px[u]; cd[u] = pd[u]; }
            if (t0 + SCAN_PF < CLEN) {
#pragma unroll
                for (int u = 0; u < SCAN_PF; u++) {
                    const size_t o = base + (size_t)(t0 + SCAN_PF + u) * DI;
                    px[u] = __half2float(g_xacth[o]);
                    pd[u] = __half2float(g_dth[o]);
                }
            }
#pragma unroll
            for (int u = 0; u < SCAN_PF; u++) {
                const float dv  = cd[u];
                const float dtx = dv * cx[u];
                sdv += dv;
#pragma unroll
                for (int s = 0; s < DS; s++)
                    h[s] = ex2f(dv * a2[s]) * h[s] + dtx;
            }
        }
        s_sdv[li] = sdv;
#pragma unroll
        for (int s = 0; s < DS; s++) s_hio[li * 17 + s] = h[s];
    }
    __syncthreads();

    // ---- Phase B ----
    if (tid < 2 * SCH) {
        const int ch2 = tid & (SCH - 1);
        const int b2  = tid >> 4;
        const int c2  = blockIdx.x * SCH + ch2;
        float a22[DS];
#pragma unroll
        for (int s = 0; s < DS; s++) a22[s] = g_A2[c2 * DS + s];
        float h[DS];
#pragma unroll
        for (int s = 0; s < DS; s++) h[s] = 0.f;
        for (int g2 = 0; g2 < GCH; g2++) {
            const int li2 = (b2 * GCH + g2) * SCH + ch2;
            const float sd = s_sdv[li2];
#pragma unroll
            for (int s = 0; s < DS; s++) {
                const float ho = s_hio[li2 * 17 + s];
                s_hio[li2 * 17 + s] = h[s];
                h[s] = ex2f(a22[s] * sd) * h[s] + ho;
            }
        }
    }
    __syncthreads();

    // ---- Phase C ----
    {
        float h[DS];
#pragma unroll
        for (int s = 0; s < DS; s++) h[s] = s_hio[li * 17 + s];
        const float dpc = Dp[c];

        float px[SCAN_PF], pd[SCAN_PF], pz[SCAN_PF];
#pragma unroll
        for (int u = 0; u < SCAN_PF; u++) {
            const size_t o = base + (size_t)u * DI;
            px[u] = __half2float(g_xacth[o]);
            pd[u] = __half2float(g_dth[o]);
            pz[u] = __half2float(g_zh[o]);
        }
        for (int t0 = 0; t0 < CLEN; t0 += SCAN_PF) {
            float cx[SCAN_PF], cd[SCAN_PF], cz[SCAN_PF];
#pragma unroll
            for (int u = 0; u < SCAN_PF; u++) { cx[u] = px[u]; cd[u] = pd[u]; cz[u] = pz[u]; }
            if (t0 + SCAN_PF < CLEN) {
#pragma unroll
                for (int u = 0; u < SCAN_PF; u++) {
                    const size_t o = base + (size_t)(t0 + SCAN_PF + u) * DI;
                    px[u] = __half2float(g_xacth[o]);
                    pd[u] = __half2float(g_dth[o]);
                    pz[u] = __half2float(g_zh[o]);
                }
            }
#pragma unroll
            for (int u = 0; u < SCAN_PF; u++) {
                const float xv  = cx[u];
                const float dv  = cd[u];
                const float dtx = dv * xv;
#pragma unroll
                for (int s = 0; s < DS; s++)
                    h[s] = ex2f(dv * a2[s]) * h[s] + dtx;
                float s0 = (h[0] + h[1]) + (h[2] + h[3]);
                float s1 = (h[4] + h[5]) + (h[6] + h[7]);
                float s2 = (h[8] + h[9]) + (h[10] + h[11]);
                float s3 = (h[12] + h[13]) + (h[14] + h[15]);
                const float sum = (s0 + s1) + (s2 + s3);
                g_ygh[base + (size_t)(t0 + u) * DI] =
                    __float2half_rn((sum + dpc * xv) * cz[u]);
            }
        }
    }
}

// ---------------- launch -------------------------------------------------------
extern "C" void kernel_launch(void* const* d_in, const int* in_sizes, int n_in,
                              void* d_out, int out_size)
{
    (void)in_sizes; (void)n_in; (void)out_size;
    const float* x     = (const float*)d_in[0];
    const float* W_in  = (const float*)d_in[1];
    const float* cw    = (const float*)d_in[2];
    const float* cb    = (const float*)d_in[3];
    const float* A_log = (const float*)d_in[4];
    const float* Dp    = (const float*)d_in[5];
    const float* W_dt  = (const float*)d_in[6];
    const float* b_dt  = (const float*)d_in[7];
    const float* W_out = (const float*)d_in[8];
    float* out = (float*)d_out;

    __half *xh, *winh, *wdth, *wouth, *xph, *zh, *dth, *xacth, *ygh;
    cudaGetSymbolAddress((void**)&xh,    g_xh);
    cudaGetSymbolAddress((void**)&winh,  g_Winh);
    cudaGetSymbolAddress((void**)&wdth,  g_Wdth);
    cudaGetSymbolAddress((void**)&wouth, g_Wouth);
    cudaGetSymbolAddress((void**)&xph,   g_xph);
    cudaGetSymbolAddress((void**)&zh,    g_zh);
    cudaGetSymbolAddress((void**)&dth,   g_dth);
    cudaGetSymbolAddress((void**)&xacth, g_xacth);
    cudaGetSymbolAddress((void**)&ygh,   g_ygh);

    cudaFuncSetAttribute(mma_gemm<2 * DI, DM, 1>,
                         cudaFuncAttributeMaxDynamicSharedMemorySize, GEMM_SMEM);
    cudaFuncSetAttribute(mma_gemm<DI, DI, 2>,
                         cudaFuncAttributeMaxDynamicSharedMemorySize, GEMM_SMEM);
    cudaFuncSetAttribute(mma_gemm<DM, DI, 0>,
                         cudaFuncAttributeMaxDynamicSharedMemorySize, GEMM_SMEM);
    cudaFuncSetAttribute(scan_fused_kernel,
                         cudaFuncAttributeMaxDynamicSharedMemorySize, SCAN_SMEM);

    constexpr int N1 = 2 * DI * DM / 4, N2 = DI * DI / 4, N3 = DM * DI / 4;

    // launches #1..#3 (profiler captures the 4th launch -> gemm1)
    prep_A2_kernel<<<(DI * DS + 255) / 256, 256>>>(A_log);
    cvtW_kernel<<<(N1 + N2 + N3 + 255) / 256, 256>>>(W_in, winh, N1,
                                                     W_dt, wdth, N2,
                                                     W_out, wouth, N3);
    cvt_kernel<<<(MM * DM / 4 + 255) / 256, 256>>>(x, xh, MM * DM / 4);

    // #4: GEMM1: x_proj | silu(z), both fp16                 <-- profiled
    mma_gemm<2 * DI, DM, 1><<<dim3((2 * DI) / TN, MM / 128), 1024, GEMM_SMEM>>>(
        xh, winh, nullptr, xph, zh, nullptr);

    // conv: 8 tokens per thread
    conv_silu_kernel<<<((MM / 8) * DI + 255) / 256, 256>>>(cw, cb);

    // GEMM2: dt = softplus(x_act @ W_dt^T + b_dt), fp16 out
    mma_gemm<DI, DI, 2><<<dim3(DI / TN, MM / 128), 1024, GEMM_SMEM>>>(
        xacth, wdth, nullptr, dth, nullptr, b_dt);

    // fused chunked scan (A + combine + C)
    scan_fused_kernel<<<DI / SCH, 1024, SCAN_SMEM>>>(Dp);

    // GEMM3: out = yg @ W_out^T (fp32 out)
    mma_gemm<DM, DI, 0><<<dim3(DM / TN, MM / 128), 1024, GEMM_SMEM>>>(
        ygh, wouth, out, nullptr, nullptr, nullptr);
}